// round 14
// baseline (speedup 1.0000x reference)
#include <cuda_runtime.h>
#include <cuda_bf16.h>
#include <math.h>
#include <stdint.h>

// ---------------- problem constants ----------------
constexpr int B = 8;
constexpr int T = 769;
constexpr int H = 8;
constexpr int NCOLS = 2048;
constexpr int BT = B * T;            // 6152
constexpr int BHT = B * H * T;       // 49216
constexpr int TP = 800;              // padded k-extent for P planes
constexpr long long X_ELEMS = (long long)BT * 512;

typedef __nv_bfloat16 bf16;

// ---------------- scratch (device globals; zero-initialized) ----------------
__device__ bf16 g_xhH[BT * 512], g_xhL[BT * 512];
__device__ bf16 g_xtH[BT * 512], g_xtL[BT * 512];
__device__ bf16 g_WhH[512 * 512], g_WhL[512 * 512];
__device__ bf16 g_WvH[512 * 512], g_WvL[512 * 512];
__device__ bf16 g_WoH[512 * 512], g_WoL[512 * 512];
__device__ bf16 g_fhH[BT * 512], g_fhL[BT * 512];
__device__ bf16 g_ftH[BT * 512], g_ftL[BT * 512];
__device__ bf16 g_fvH[BT * 512], g_fvL[BT * 512];
__device__ bf16 g_xaH[BT * 512], g_xaL[BT * 512];
__device__ bf16 g_chH[BHT * 32], g_chL[BHT * 32];
__device__ bf16 g_ctH[BHT * 32], g_ctL[BHT * 32];
__device__ float g_chf[BHT * 24], g_ctf[BHT * 24];
__device__ bf16 g_pH[(size_t)BHT * TP], g_pL[(size_t)BHT * TP];

// ================= helpers =================
__device__ __forceinline__ void ldsm_x4(uint32_t* r, uint32_t addr) {
    asm volatile("ldmatrix.sync.aligned.m8n8.x4.shared.b16 {%0,%1,%2,%3}, [%4];"
                 : "=r"(r[0]), "=r"(r[1]), "=r"(r[2]), "=r"(r[3]) : "r"(addr));
}
__device__ __forceinline__ void ldsm_x4_t(uint32_t* r, uint32_t addr) {
    asm volatile("ldmatrix.sync.aligned.m8n8.x4.trans.shared.b16 {%0,%1,%2,%3}, [%4];"
                 : "=r"(r[0]), "=r"(r[1]), "=r"(r[2]), "=r"(r[3]) : "r"(addr));
}
__device__ __forceinline__ void mma_bf16(float* c, const uint32_t* a, uint32_t b0, uint32_t b1) {
    asm volatile("mma.sync.aligned.m16n8k16.row.col.f32.bf16.bf16.f32 "
                 "{%0,%1,%2,%3}, {%4,%5,%6,%7}, {%8,%9}, {%0,%1,%2,%3};"
                 : "+f"(c[0]), "+f"(c[1]), "+f"(c[2]), "+f"(c[3])
                 : "r"(a[0]), "r"(a[1]), "r"(a[2]), "r"(a[3]), "r"(b0), "r"(b1));
}
__device__ __forceinline__ uint32_t smem_addr(const void* p) {
    return (uint32_t)__cvta_generic_to_shared(p);
}
__device__ __forceinline__ void cp16(uint32_t dst, const void* src, int bytes) {
    asm volatile("cp.async.cg.shared.global [%0], [%1], 16, %2;"
                 :: "r"(dst), "l"(src), "r"(bytes));
}
#define CP_COMMIT() asm volatile("cp.async.commit_group;")
#define CP_WAIT(n)  asm volatile("cp.async.wait_group %0;" :: "n"(n))

__device__ __forceinline__ void split4(float4 v, uint2& hi, uint2& lo) {
    float f[4] = {v.x, v.y, v.z, v.w};
    float fh[4], fl[4];
#pragma unroll
    for (int j = 0; j < 4; j++) {
        fh[j] = __bfloat162float(__float2bfloat16_rn(f[j]));
        fl[j] = f[j] - fh[j];
    }
    union { __nv_bfloat162 h2[2]; uint2 u; } a, b;
    a.h2[0] = __floats2bfloat162_rn(fh[0], fh[1]);
    a.h2[1] = __floats2bfloat162_rn(fh[2], fh[3]);
    b.h2[0] = __floats2bfloat162_rn(fl[0], fl[1]);
    b.h2[1] = __floats2bfloat162_rn(fl[2], fl[3]);
    hi = a.u; lo = b.u;
}
__device__ __forceinline__ void split2(float x, float y, uint32_t& hi, uint32_t& lo) {
    float hx = __bfloat162float(__float2bfloat16_rn(x));
    float hy = __bfloat162float(__float2bfloat16_rn(y));
    union { __nv_bfloat162 h2; uint32_t u; } a, b;
    a.h2 = __floats2bfloat162_rn(hx, hy);
    b.h2 = __floats2bfloat162_rn(x - hx, y - hy);
    hi = a.u; lo = b.u;
}

// ================= fused convert (5 tensors) + gather/normalize =================
__global__ void prep_kernel(const float* __restrict__ xh, const float* __restrict__ xt,
                            const float* __restrict__ Wh, const float* __restrict__ Wv,
                            const float* __restrict__ Wo,
                            const float* __restrict__ colh, const float* __restrict__ colt,
                            const int* __restrict__ ids)
{
    const int t = blockIdx.y;
    if (t < 5) {
        const int n4 = (t < 2) ? (BT * 512 / 4) : (512 * 512 / 4);
        const int i = blockIdx.x * blockDim.x + threadIdx.x;
        if (i >= n4) return;
        const float* in; bf16 *hi, *lo;
        switch (t) {
            case 0: in = xh; hi = g_xhH; lo = g_xhL; break;
            case 1: in = xt; hi = g_xtH; lo = g_xtL; break;
            case 2: in = Wh; hi = g_WhH; lo = g_WhL; break;
            case 3: in = Wv; hi = g_WvH; lo = g_WvL; break;
            default: in = Wo; hi = g_WoH; lo = g_WoL; break;
        }
        float4 v = ((const float4*)in)[i];
        uint2 h, l; split4(v, h, l);
        ((uint2*)hi)[i] = h;
        ((uint2*)lo)[i] = l;
        return;
    }
    // t == 5: gather + L2 normalize (warp per row)
    const int w = (blockIdx.x * blockDim.x + threadIdx.x) >> 5;
    const int lane = threadIdx.x & 31;
    if (w >= BHT) return;
    const int q = w % T;
    const int bh = w / T;
    const int h = bh & 7, b = bh >> 3;
    const int srow = (q == 0) ? 0 : (ids[b * (T - 1) + (q - 1)] + 1);
    {
        float v = (lane < 22) ? colh[((size_t)h * NCOLS + srow) * 22 + lane] : 0.f;
        float ss = v * v;
#pragma unroll
        for (int o = 16; o; o >>= 1) ss += __shfl_xor_sync(0xffffffffu, ss, o);
        float nv = (lane < 22) ? v / sqrtf(ss) : 0.f;
        if (lane < 24) g_chf[(size_t)w * 24 + lane] = nv;
        bf16 hi = __float2bfloat16_rn(nv);
        g_chH[(size_t)w * 32 + lane] = hi;
        g_chL[(size_t)w * 32 + lane] = __float2bfloat16_rn(nv - __bfloat162float(hi));
    }
    {
        float v = (lane < 22) ? colt[((size_t)h * NCOLS + srow) * 22 + lane] : 0.f;
        float ss = v * v;
#pragma unroll
        for (int o = 16; o; o >>= 1) ss += __shfl_xor_sync(0xffffffffu, ss, o);
        float nv = (lane < 22) ? v / sqrtf(ss) : 0.f;
        if (lane < 24) g_ctf[(size_t)w * 24 + lane] = nv;
        bf16 hi = __float2bfloat16_rn(nv);
        g_ctH[(size_t)w * 32 + lane] = hi;
        g_ctL[(size_t)w * 32 + lane] = __float2bfloat16_rn(nv - __bfloat162float(hi));
    }
}

// ================= batched pipelined HMMA GEMM (2 CTAs/SM) =================
struct Job {
    const bf16 *AH, *AL, *WH, *WL;
    const float *bias, *scale;
    float* Cf;
    bf16 *CH, *CL;
};
struct Jobs3 { Job j[3]; };

constexpr uint32_t GEMM_SMEM = 2 * 4 * 128 * 40 * 2;   // 81920
constexpr uint32_t G_PL = 128 * 40 * 2;
constexpr uint32_t G_ST = 4 * G_PL;

__global__ __launch_bounds__(256, 2) void gemm_batched(Jobs3 jobs, int M)
{
    extern __shared__ char dsm[];
    const Job J = jobs.j[blockIdx.z];
    const uint32_t sm = smem_addr(dsm);
    const int tid = threadIdx.x;
    const int wid = tid >> 5, lane = tid & 31;
    const int wm = wid & 3, wn = wid >> 2;
    const int m0 = blockIdx.y * 128, n0 = blockIdx.x * 128;
    const int a_r = lane & 15, a_c = (lane >> 4) * 8;
    const int b_r = lane & 7,  b_c = (lane >> 3) * 8;

    float acc[2][8][4];
#pragma unroll
    for (int mi = 0; mi < 2; mi++)
#pragma unroll
        for (int ni = 0; ni < 8; ni++)
#pragma unroll
            for (int r = 0; r < 4; r++) acc[mi][ni][r] = 0.f;

    const int r0 = tid >> 2, c0 = (tid & 3) * 8;
    const int r1 = (tid + 256) >> 2, c1 = ((tid + 256) & 3) * 8;

    auto load_stage = [&](int st, int chunk) {
        const int k0 = chunk * 32;
        const uint32_t base = sm + st * G_ST;
#pragma unroll
        for (int i = 0; i < 2; i++) {
            const int row = i ? r1 : r0, cs = i ? c1 : c0;
            const int gr = m0 + row;
            const int grc = (gr < M) ? gr : (M - 1);
            const int ab = (gr < M) ? 16 : 0;
            const size_t aoff = (size_t)grc * 512 + k0 + cs;
            const size_t woff = (size_t)(n0 + row) * 512 + k0 + cs;
            const uint32_t so = (row * 40 + cs) * 2;
            cp16(base + so,            J.AH + aoff, ab);
            cp16(base + G_PL + so,     J.AL + aoff, ab);
            cp16(base + 2 * G_PL + so, J.WH + woff, 16);
            cp16(base + 3 * G_PL + so, J.WL + woff, 16);
        }
    };

    load_stage(0, 0);
    CP_COMMIT();

    for (int chunk = 0; chunk < 16; chunk++) {
        const int st = chunk & 1;
        if (chunk + 1 < 16) {
            load_stage(st ^ 1, chunk + 1);
            CP_COMMIT();
            CP_WAIT(1);
        } else {
            CP_WAIT(0);
        }
        __syncthreads();

        bf16 (*AsH)[40] = (bf16(*)[40])(dsm + st * G_ST);
        bf16 (*AsL)[40] = (bf16(*)[40])(dsm + st * G_ST + G_PL);
        bf16 (*BsH)[40] = (bf16(*)[40])(dsm + st * G_ST + 2 * G_PL);
        bf16 (*BsL)[40] = (bf16(*)[40])(dsm + st * G_ST + 3 * G_PL);

        uint32_t ah[2][2][4], al[2][2][4];
#pragma unroll
        for (int mi = 0; mi < 2; mi++) {
            const int r = wm * 32 + mi * 16 + a_r;
#pragma unroll
            for (int ks = 0; ks < 2; ks++) {
                const int c = ks * 16 + a_c;
                ldsm_x4(ah[mi][ks], smem_addr(&AsH[r][c]));
                ldsm_x4(al[mi][ks], smem_addr(&AsL[r][c]));
            }
        }
#pragma unroll
        for (int ni = 0; ni < 8; ni++) {
            const int r = wn * 64 + ni * 8 + b_r;
            uint32_t bh4[4], bl4[4];
            ldsm_x4(bh4, smem_addr(&BsH[r][b_c]));
            ldsm_x4(bl4, smem_addr(&BsL[r][b_c]));
#pragma unroll
            for (int mi = 0; mi < 2; mi++) {
#pragma unroll
                for (int ks = 0; ks < 2; ks++) {
                    mma_bf16(acc[mi][ni], ah[mi][ks], bh4[2 * ks], bh4[2 * ks + 1]);
                    mma_bf16(acc[mi][ni], ah[mi][ks], bl4[2 * ks], bl4[2 * ks + 1]);
                    mma_bf16(acc[mi][ni], al[mi][ks], bh4[2 * ks], bh4[2 * ks + 1]);
                }
            }
        }
        __syncthreads();
    }

    const int tr = lane >> 2, tc = (lane & 3) * 2;
#pragma unroll
    for (int mi = 0; mi < 2; mi++) {
#pragma unroll
        for (int ni = 0; ni < 8; ni++) {
            const int n = n0 + wn * 64 + ni * 8 + tc;
            const float b0 = J.bias[n], b1 = J.bias[n + 1];
            float s0 = 1.f, s1 = 1.f;
            if (J.scale) { s0 = J.scale[n]; s1 = J.scale[n + 1]; }
#pragma unroll
            for (int half = 0; half < 2; half++) {
                const int m = m0 + wm * 32 + mi * 16 + tr + half * 8;
                if (m >= M) continue;
                const float x = (acc[mi][ni][half * 2 + 0] + b0) * s0;
                const float y = (acc[mi][ni][half * 2 + 1] + b1) * s1;
                const size_t off = (size_t)m * 512 + n;
                if (J.Cf) *(float2*)(J.Cf + off) = make_float2(x, y);
                if (J.CH) {
                    uint32_t hi, lo; split2(x, y, hi, lo);
                    *(uint32_t*)(J.CH + off) = hi;
                    *(uint32_t*)(J.CL + off) = lo;
                }
            }
        }
    }
}

// ================= logits: 64q x 64k tile, 3 CTAs/SM (known good) =================
constexpr uint32_t LOGITS_SMEM = 36864;
constexpr float RESCUE_BAND = 1e-4f;

__global__ __launch_bounds__(256, 3) void logits_hmma(const float* __restrict__ bias,
                                                      float* __restrict__ FR)
{
    extern __shared__ char dsm[];
    const uint32_t sm = smem_addr(dsm);
    const int tid = threadIdx.x;
    const int wid = tid >> 5, lane = tid & 31;
    const int wm = wid & 1, wn = wid >> 1;           // 2 m-warps x 4 n-warps
    const int bh = blockIdx.z, b = bh >> 3, h = bh & 7;
    const int q0 = blockIdx.y * 64, k0 = blockIdx.x * 64;
    const int a_r = lane & 15, a_c = (lane >> 4) * 8;
    const int b_r = lane & 7,  b_c = (lane >> 3) * 8;
    const int tr = lane >> 2,  tc = (lane & 3) * 2;
    const float bias0 = bias[0];

    // ---- load phase A ----
    {
        const int row = tid >> 2, cs = (tid & 3) * 8;
        const int q = q0 + row, k = k0 + row;
        const int qc = (q < T) ? q : (T - 1), kc = (k < T) ? k : (T - 1);
        const int qb = (q < T) ? 16 : 0, kb = (k < T) ? 16 : 0;
        const size_t qoff = ((size_t)bh * T + qc) * 32 + cs;
        const size_t koff = ((size_t)bh * T + kc) * 32 + cs;
        const uint32_t so = row * 80 + cs * 2;
        cp16(sm + so,         g_chH + qoff, qb);
        cp16(sm + 5120 + so,  g_chL + qoff, qb);
        cp16(sm + 10240 + so, g_ctH + koff, kb);
        cp16(sm + 15360 + so, g_ctL + koff, kb);
    }
    CP_COMMIT();
    CP_WAIT(0);
    __syncthreads();

    float acc[2][2][4];
#pragma unroll
    for (int mi = 0; mi < 2; mi++)
#pragma unroll
        for (int ni = 0; ni < 2; ni++)
#pragma unroll
            for (int r = 0; r < 4; r++) acc[mi][ni][r] = 0.f;

    // ---- phase A ----
    {
        bf16 (*QH)[40] = (bf16(*)[40])(dsm);
        bf16 (*QL)[40] = (bf16(*)[40])(dsm + 5120);
        bf16 (*KH)[40] = (bf16(*)[40])(dsm + 10240);
        bf16 (*KL)[40] = (bf16(*)[40])(dsm + 15360);
        uint32_t ah[2][2][4], al[2][2][4];
#pragma unroll
        for (int mi = 0; mi < 2; mi++) {
            const int r = wm * 32 + mi * 16 + a_r;
#pragma unroll
            for (int ks = 0; ks < 2; ks++) {
                ldsm_x4(ah[mi][ks], smem_addr(&QH[r][ks * 16 + a_c]));
                ldsm_x4(al[mi][ks], smem_addr(&QL[r][ks * 16 + a_c]));
            }
        }
#pragma unroll
        for (int ni = 0; ni < 2; ni++) {
            const int r = wn * 16 + ni * 8 + b_r;
            uint32_t bh4[4], bl4[4];
            ldsm_x4(bh4, smem_addr(&KH[r][b_c]));
            ldsm_x4(bl4, smem_addr(&KL[r][b_c]));
#pragma unroll
            for (int mi = 0; mi < 2; mi++) {
#pragma unroll
                for (int ks = 0; ks < 2; ks++) {
                    mma_bf16(acc[mi][ni], ah[mi][ks], bh4[2 * ks], bh4[2 * ks + 1]);
                    mma_bf16(acc[mi][ni], ah[mi][ks], bl4[2 * ks], bl4[2 * ks + 1]);
                    mma_bf16(acc[mi][ni], al[mi][ks], bh4[2 * ks], bh4[2 * ks + 1]);
                }
            }
        }
    }
    __syncthreads();

    // ---- issue phase B loads ----
#pragma unroll
    for (int i = 0; i < 2; i++) {
        const int s = tid + 256 * i;
        const int row = s >> 3, cs = (s & 7) * 8;
        const int q = q0 + row, k = k0 + row;
        const int qc = (q < T) ? q : (T - 1), kc = (k < T) ? k : (T - 1);
        const int qb = (q < T) ? 16 : 0, kb = (k < T) ? 16 : 0;
        const size_t xoff = ((size_t)(b * T + qc)) * 512 + h * 64 + cs;
        const size_t yoff = ((size_t)(b * T + kc)) * 512 + h * 64 + cs;
        const uint32_t so = row * 144 + cs * 2;
        cp16(sm + so,         g_fhH + xoff, qb);
        cp16(sm + 9216 + so,  g_fhL + xoff, qb);
        cp16(sm + 18432 + so, g_ftH + yoff, kb);
        cp16(sm + 27648 + so, g_ftL + yoff, kb);
    }
    CP_COMMIT();

    // ---- masks ----
    uint32_t adjm = 0u, unc = 0u;
#pragma unroll
    for (int mi = 0; mi < 2; mi++)
#pragma unroll
        for (int ni = 0; ni < 2; ni++)
#pragma unroll
            for (int r = 0; r < 4; r++) {
                const int q = q0 + wm * 32 + mi * 16 + tr + (r >> 1) * 8;
                const int k = k0 + wn * 16 + ni * 8 + tc + (r & 1);
                const bool valid = (q < T) && (k < T) && (k != 0) && (k != q);
                if (valid) {
                    const float ts = acc[mi][ni][r] + bias0;
                    const int idx = (mi * 2 + ni) * 4 + r;
                    if (fabsf(ts) < RESCUE_BAND) unc |= 1u << idx;
                    if (ts > 0.f)                adjm |= 1u << idx;
                }
            }

    // ---- phase B ----
#pragma unroll
    for (int mi = 0; mi < 2; mi++)
#pragma unroll
        for (int ni = 0; ni < 2; ni++)
#pragma unroll
            for (int r = 0; r < 4; r++) acc[mi][ni][r] = 0.f;

    CP_WAIT(0);
    __syncthreads();
    {
        bf16 (*XH)[72] = (bf16(*)[72])(dsm);
        bf16 (*XL)[72] = (bf16(*)[72])(dsm + 9216);
        bf16 (*YH)[72] = (bf16(*)[72])(dsm + 18432);
        bf16 (*YL)[72] = (bf16(*)[72])(dsm + 27648);
#pragma unroll
        for (int kk = 0; kk < 64; kk += 32) {
            uint32_t ah[2][2][4], al[2][2][4];
#pragma unroll
            for (int mi = 0; mi < 2; mi++) {
                const int r = wm * 32 + mi * 16 + a_r;
#pragma unroll
                for (int ks = 0; ks < 2; ks++) {
                    const int c = kk + ks * 16 + a_c;
                    ldsm_x4(ah[mi][ks], smem_addr(&XH[r][c]));
                    ldsm_x4(al[mi][ks], smem_addr(&XL[r][c]));
                }
            }
#pragma unroll
            for (int ni = 0; ni < 2; ni++) {
                const int r = wn * 16 + ni * 8 + b_r;
                uint32_t bh4[4], bl4[4];
                ldsm_x4(bh4, smem_addr(&YH[r][kk + b_c]));
                ldsm_x4(bl4, smem_addr(&YL[r][kk + b_c]));
#pragma unroll
                for (int mi = 0; mi < 2; mi++) {
#pragma unroll
                    for (int ks = 0; ks < 2; ks++) {
                        mma_bf16(acc[mi][ni], ah[mi][ks], bh4[2 * ks], bh4[2 * ks + 1]);
                        mma_bf16(acc[mi][ni], ah[mi][ks], bl4[2 * ks], bl4[2 * ks + 1]);
                        mma_bf16(acc[mi][ni], al[mi][ks], bh4[2 * ks], bh4[2 * ks + 1]);
                    }
                }
            }
        }
    }
    __syncthreads();

    // ---- stage masked logits into smem tile ----
    {
        float (*stg)[68] = (float(*)[68])dsm;
#pragma unroll
        for (int mi = 0; mi < 2; mi++) {
#pragma unroll
            for (int ni = 0; ni < 2; ni++) {
#pragma unroll
                for (int r = 0; r < 4; r++) {
                    const int ql = wm * 32 + mi * 16 + tr + (r >> 1) * 8;
                    const int kl = wn * 16 + ni * 8 + tc + (r & 1);
                    const int idx = (mi * 2 + ni) * 4 + r;
                    bool abit;
                    if ((unc >> idx) & 1u) {
                        const float* cq = g_chf + ((size_t)bh * T + q0 + ql) * 24;
                        const float* ck = g_ctf + ((size_t)bh * T + k0 + kl) * 24;
                        float d = 0.f;
#pragma unroll
                        for (int c = 0; c < 22; c++) d = fmaf(cq[c], ck[c], d);
                        abit = (d + bias0 > 0.f);
                    } else {
                        abit = (adjm >> idx) & 1u;
                    }
                    float v = acc[mi][ni][r] * 0.125f;
                    if (!abit) v -= 10000.0f;
                    stg[ql][kl] = v;
                }
            }
        }
    }
    __syncthreads();

    // ---- coalesced FR store ----
    {
        float (*stg)[68] = (float(*)[68])dsm;
        const int kmax = T - k0;
#pragma unroll
        for (int r = 0; r < 8; r++) {
            const int row = wid * 8 + r;
            const int q = q0 + row;
            if (q >= T) break;
            float* fr = FR + ((size_t)bh * T + q) * T + k0;
#pragma unroll
            for (int j = 0; j < 2; j++) {
                const int col = lane + 32 * j;
                if (col < kmax) fr[col] = stg[row][col];
            }
        }
    }
}

// ================= softmax: single-pass (no max subtraction; logits are O(1)) =================
__global__ __launch_bounds__(256) void softmax_kernel(float* __restrict__ FR)
{
    __shared__ float sred[8];
    const int tid = threadIdx.x;
    const int wid = tid >> 5, lane = tid & 31;
    float* base = FR + (size_t)blockIdx.x * T;
    bf16* ph = g_pH + (size_t)blockIdx.x * TP;
    bf16* pl = g_pL + (size_t)blockIdx.x * TP;

    // single read pass: e = exp(v), accumulate sum (masked logits ~ -1e4 underflow to 0)
    float e[4];
    int n = 0;
    float s = 0.f;
    for (int i = tid; i < T; i += 256) { e[n] = __expf(base[i]); s += e[n]; n++; }
#pragma unroll
    for (int o = 16; o; o >>= 1) s += __shfl_xor_sync(0xffffffffu, s, o);
    if (lane == 0) sred[wid] = s;
    __syncthreads();
    s = 0.f;
#pragma unroll
    for (int w = 0; w < 8; w++) s += sred[w];
    const float inv = 1.0f / s;
    n = 0;
    for (int i = tid; i < T; i += 256) {
        const float p = e[n] * inv;
        base[i] = p;
        const bf16 hi = __float2bfloat16_rn(p);
        ph[i] = hi;
        pl[i] = __float2bfloat16_rn(p - __bfloat162float(hi));
        n++;
    }
}

// ================= pipelined AV (R10 structure + occupancy cap) =================
constexpr uint32_t AV_PP = 128 * 40 * 2;
constexpr uint32_t AV_VP = 32 * 72 * 2;
constexpr uint32_t AV_ST = 2 * AV_PP + 2 * AV_VP;
constexpr uint32_t AV_SMEM = 2 * AV_ST;

__global__ __launch_bounds__(256, 2) void av_hmma()
{
    extern __shared__ char dsm[];
    const uint32_t sm = smem_addr(dsm);
    const int tid = threadIdx.x;
    const int wid = tid >> 5, lane = tid & 31;
    const int wm = wid & 3, wn = wid >> 2;
    const int bh = blockIdx.y, b = bh >> 3, h = bh & 7;
    const int q0 = blockIdx.x * 128;
    const int a_r = lane & 15, a_c = (lane >> 4) * 8;
    const int tr = lane >> 2, tc = (lane & 3) * 2;

    float acc[2][4][4];
#pragma unroll
    for (int mi = 0; mi < 2; mi++)
#pragma unroll
        for (int ni = 0; ni < 4; ni++)
#pragma unroll
            for (int r = 0; r < 4; r++) acc[mi][ni][r] = 0.f;

    const int pr0 = tid >> 2, pc0 = (tid & 3) * 8;
    const int pr1 = (tid + 256) >> 2, pc1 = ((tid + 256) & 3) * 8;
    const int vr = tid >> 3, vc = (tid & 7) * 8;

    auto load_stage = [&](int st, int k0) {
        const uint32_t base = sm + st * AV_ST;
#pragma unroll
        for (int i = 0; i < 2; i++) {
            const int row = i ? pr1 : pr0, c8 = i ? pc1 : pc0;
            const int q = q0 + row;
            const int qc = (q < T) ? q : (T - 1);
            const int pb = (q < T) ? 16 : 0;
            const size_t off = ((size_t)bh * T + qc) * TP + k0 + c8;
            const uint32_t so = (row * 40 + c8) * 2;
            cp16(base + so,         g_pH + off, pb);
            cp16(base + AV_PP + so, g_pL + off, pb);
        }
        {
            const int kv = k0 + vr;
            const int kc = (kv < T) ? kv : (T - 1);
            const int vb = (kv < T) ? 16 : 0;
            const size_t off = ((size_t)(b * T + kc)) * 512 + h * 64 + vc;
            const uint32_t so = (vr * 72 + vc) * 2;
            cp16(base + 2 * AV_PP + so,         g_fvH + off, vb);
            cp16(base + 2 * AV_PP + AV_VP + so, g_fvL + off, vb);
        }
    };

    load_stage(0, 0);
    CP_COMMIT();

    constexpr int NCHUNK = TP / 32;
    for (int chunk = 0; chunk < NCHUNK; chunk++) {
        const int st = chunk & 1;
        if (chunk + 1 < NCHUNK) {
            load_stage(st ^ 1, (chunk + 1) * 32);
            CP_COMMIT();
            CP_WAIT(1);
        } else {
            CP_WAIT(0);
        }
        __syncthreads();

        bf16 (*PsH)[40] = (bf16(*)[40])(dsm + st * AV_ST);
        bf16 (*PsL)[40] = (bf16(*)[40])(dsm + st * AV_ST + AV_PP);
        bf16 (*VsH)[72] = (bf16(*)[72])(dsm + st * AV_ST + 2 * AV_PP);
        bf16 (*VsL)[72] = (bf16(*)[72])(dsm + st * AV_ST + 2 * AV_PP + AV_VP);

        uint32_t ah[2][2][4], al[2][2][4];
#pragma unroll
        for (int mi = 0; mi < 2; mi++) {
            const int r = wm * 32 + mi * 16 + a_r;
#pragma unroll
            for (int ks = 0; ks < 2; ks++) {
                const int c = ks * 16 + a_c;
                ldsm_x4(ah[mi][ks], smem_addr(&PsH[r][c]));
                ldsm_x4(al[mi][ks], smem_addr(&PsL[r][c]));
            }
        }
#pragma unroll
        for (int ni = 0; ni < 4; ni++) {
            const int nb = wn * 32 + ni * 8;
            uint32_t bh4[4], bl4[4];
            ldsm_x4_t(bh4, smem_addr(&VsH[lane][nb]));
            ldsm_x4_t(bl4, smem_addr(&VsL[lane][nb]));
#pragma unroll
            for (int mi = 0; mi < 2; mi++) {
#pragma unroll
                for (int ks = 0; ks < 2; ks++) {
                    mma_bf16(acc[mi][ni], ah[mi][ks], bh4[2 * ks], bh4[2 * ks + 1]);
                    mma_bf16(acc[mi][ni], ah[mi][ks], bl4[2 * ks], bl4[2 * ks + 1]);
                    mma_bf16(acc[mi][ni], al[mi][ks], bh4[2 * ks], bh4[2 * ks + 1]);
                }
            }
        }
        __syncthreads();
    }

#pragma unroll
    for (int mi = 0; mi < 2; mi++) {
#pragma unroll
        for (int ni = 0; ni < 4; ni++) {
            const int n = wn * 32 + ni * 8 + tc;
#pragma unroll
            for (int half = 0; half < 2; half++) {
                const int q = q0 + wm * 32 + mi * 16 + tr + half * 8;
                if (q >= T) continue;
                const float x = acc[mi][ni][half * 2 + 0];
                const float y = acc[mi][ni][half * 2 + 1];
                uint32_t hi, lo; split2(x, y, hi, lo);
                const size_t off = ((size_t)(b * T + q)) * 512 + h * 64 + n;
                *(uint32_t*)(g_xaH + off) = hi;
                *(uint32_t*)(g_xaL + off) = lo;
            }
        }
    }
}

// ---------------- launcher ----------------
extern "C" void kernel_launch(void* const* d_in, const int* in_sizes, int n_in,
                              void* d_out, int out_size)
{
    const float* x_head = (const float*)d_in[0];
    const float* x_tail = (const float*)d_in[1];
    const int*   ids    = (const int*)  d_in[2];
    const float* Wh     = (const float*)d_in[3];
    const float* bh     = (const float*)d_in[4];
    const float* Wv     = (const float*)d_in[5];
    const float* bv     = (const float*)d_in[6];
    const float* Wo     = (const float*)d_in[7];
    const float* bo     = (const float*)d_in[8];
    const float* rel    = (const float*)d_in[9];
    const float* colh   = (const float*)d_in[10];
    const float* colt   = (const float*)d_in[11];
    const float* bias   = (const float*)d_in[12];

    float* out = (float*)d_out;
    float* FR  = out + X_ELEMS;

    bf16 *xhH, *xhL, *xtH, *xtL, *WhH, *WhL, *WvH, *WvL, *WoH, *WoL;
    bf16 *fhH, *fhL, *ftH, *ftL, *fvH, *fvL, *xaH, *xaL;
    cudaGetSymbolAddress((void**)&xhH, g_xhH); cudaGetSymbolAddress((void**)&xhL, g_xhL);
    cudaGetSymbolAddress((void**)&xtH, g_xtH); cudaGetSymbolAddress((void**)&xtL, g_xtL);
    cudaGetSymbolAddress((void**)&WhH, g_WhH); cudaGetSymbolAddress((void**)&WhL, g_WhL);
    cudaGetSymbolAddress((void**)&WvH, g_WvH); cudaGetSymbolAddress((void**)&WvL, g_WvL);
    cudaGetSymbolAddress((void**)&WoH, g_WoH); cudaGetSymbolAddress((void**)&WoL, g_WoL);
    cudaGetSymbolAddress((void**)&fhH, g_fhH); cudaGetSymbolAddress((void**)&fhL, g_fhL);
    cudaGetSymbolAddress((void**)&ftH, g_ftH); cudaGetSymbolAddress((void**)&ftL, g_ftL);
    cudaGetSymbolAddress((void**)&fvH, g_fvH); cudaGetSymbolAddress((void**)&fvL, g_fvL);
    cudaGetSymbolAddress((void**)&xaH, g_xaH); cudaGetSymbolAddress((void**)&xaL, g_xaL);

    cudaFuncSetAttribute(gemm_batched, cudaFuncAttributeMaxDynamicSharedMemorySize, GEMM_SMEM);
    cudaFuncSetAttribute(logits_hmma, cudaFuncAttributeMaxDynamicSharedMemorySize, LOGITS_SMEM);
    cudaFuncSetAttribute(av_hmma, cudaFuncAttributeMaxDynamicSharedMemorySize, AV_SMEM);

    // launch 1: fused convert + gather
    prep_kernel<<<dim3(6152, 6), 256>>>(x_head, x_tail, Wh, Wv, Wo, colh, colt, ids);
    // launch 2: projections
    Jobs3 pj;
    pj.j[0] = { xhH, xhL, WhH, WhL, bh, rel,     nullptr, fhH, fhL };
    pj.j[1] = { xtH, xtL, WhH, WhL, bh, nullptr, nullptr, ftH, ftL };
    pj.j[2] = { xtH, xtL, WvH, WvL, bv, nullptr, nullptr, fvH, fvL };
    gemm_batched<<<dim3(4, (BT + 127) / 128, 3), 256, GEMM_SMEM>>>(pj, BT);
    // launch 3: logits (64q x 64k tiles)
    dim3 gLog((T + 63) / 64, (T + 63) / 64, B * H);   // (13, 13, 64)
    logits_hmma<<<gLog, 256, LOGITS_SMEM>>>(bias, FR);
    // launch 4: softmax (profiled slot)
    softmax_kernel<<<B * H * T, 256>>>(FR);
    // launch 5: AV
    dim3 gAV((T + 127) / 128, B * H);
    av_hmma<<<gAV, 256, AV_SMEM>>>();
    // launch 6: output projection
    Jobs3 oj;
    oj.j[0] = { xaH, xaL, WoH, WoL, bo, nullptr, out, nullptr, nullptr };
    oj.j[1] = oj.j[0];
    oj.j[2] = oj.j[0];
    gemm_batched<<<dim3(4, (BT + 127) / 128, 1), 256, GEMM_SMEM>>>(oj, BT);
}

// round 15
// speedup vs baseline: 1.0185x; 1.0185x over previous
#include <cuda_runtime.h>
#include <cuda_bf16.h>
#include <math.h>
#include <stdint.h>

// ---------------- problem constants ----------------
constexpr int B = 8;
constexpr int T = 769;
constexpr int H = 8;
constexpr int NCOLS = 2048;
constexpr int BT = B * T;            // 6152
constexpr int BHT = B * H * T;       // 49216
constexpr int TP = 800;              // padded k-extent for P planes
constexpr long long X_ELEMS = (long long)BT * 512;

typedef __nv_bfloat16 bf16;

// ---------------- scratch (device globals; zero-initialized) ----------------
__device__ bf16 g_xhH[BT * 512], g_xhL[BT * 512];
__device__ bf16 g_xtH[BT * 512], g_xtL[BT * 512];
__device__ bf16 g_WhH[512 * 512], g_WhL[512 * 512];
__device__ bf16 g_WvH[512 * 512], g_WvL[512 * 512];
__device__ bf16 g_WoH[512 * 512], g_WoL[512 * 512];
__device__ bf16 g_fhH[BT * 512], g_fhL[BT * 512];
__device__ bf16 g_ftH[BT * 512], g_ftL[BT * 512];
__device__ bf16 g_fvH[BT * 512], g_fvL[BT * 512];
__device__ bf16 g_xaH[BT * 512], g_xaL[BT * 512];
__device__ bf16 g_chH[BHT * 32], g_chL[BHT * 32];
__device__ bf16 g_ctH[BHT * 32], g_ctL[BHT * 32];
__device__ float g_chf[BHT * 24], g_ctf[BHT * 24];
__device__ bf16 g_pH[(size_t)BHT * TP], g_pL[(size_t)BHT * TP];

// ================= helpers =================
__device__ __forceinline__ void ldsm_x4(uint32_t* r, uint32_t addr) {
    asm volatile("ldmatrix.sync.aligned.m8n8.x4.shared.b16 {%0,%1,%2,%3}, [%4];"
                 : "=r"(r[0]), "=r"(r[1]), "=r"(r[2]), "=r"(r[3]) : "r"(addr));
}
__device__ __forceinline__ void ldsm_x4_t(uint32_t* r, uint32_t addr) {
    asm volatile("ldmatrix.sync.aligned.m8n8.x4.trans.shared.b16 {%0,%1,%2,%3}, [%4];"
                 : "=r"(r[0]), "=r"(r[1]), "=r"(r[2]), "=r"(r[3]) : "r"(addr));
}
__device__ __forceinline__ void mma_bf16(float* c, const uint32_t* a, uint32_t b0, uint32_t b1) {
    asm volatile("mma.sync.aligned.m16n8k16.row.col.f32.bf16.bf16.f32 "
                 "{%0,%1,%2,%3}, {%4,%5,%6,%7}, {%8,%9}, {%0,%1,%2,%3};"
                 : "+f"(c[0]), "+f"(c[1]), "+f"(c[2]), "+f"(c[3])
                 : "r"(a[0]), "r"(a[1]), "r"(a[2]), "r"(a[3]), "r"(b0), "r"(b1));
}
__device__ __forceinline__ uint32_t smem_addr(const void* p) {
    return (uint32_t)__cvta_generic_to_shared(p);
}
__device__ __forceinline__ void cp16(uint32_t dst, const void* src, int bytes) {
    asm volatile("cp.async.cg.shared.global [%0], [%1], 16, %2;"
                 :: "r"(dst), "l"(src), "r"(bytes));
}
#define CP_COMMIT() asm volatile("cp.async.commit_group;")
#define CP_WAIT(n)  asm volatile("cp.async.wait_group %0;" :: "n"(n))

__device__ __forceinline__ void split4(float4 v, uint2& hi, uint2& lo) {
    float f[4] = {v.x, v.y, v.z, v.w};
    float fh[4], fl[4];
#pragma unroll
    for (int j = 0; j < 4; j++) {
        fh[j] = __bfloat162float(__float2bfloat16_rn(f[j]));
        fl[j] = f[j] - fh[j];
    }
    union { __nv_bfloat162 h2[2]; uint2 u; } a, b;
    a.h2[0] = __floats2bfloat162_rn(fh[0], fh[1]);
    a.h2[1] = __floats2bfloat162_rn(fh[2], fh[3]);
    b.h2[0] = __floats2bfloat162_rn(fl[0], fl[1]);
    b.h2[1] = __floats2bfloat162_rn(fl[2], fl[3]);
    hi = a.u; lo = b.u;
}
__device__ __forceinline__ void split2(float x, float y, uint32_t& hi, uint32_t& lo) {
    float hx = __bfloat162float(__float2bfloat16_rn(x));
    float hy = __bfloat162float(__float2bfloat16_rn(y));
    union { __nv_bfloat162 h2; uint32_t u; } a, b;
    a.h2 = __floats2bfloat162_rn(hx, hy);
    b.h2 = __floats2bfloat162_rn(x - hx, y - hy);
    hi = a.u; lo = b.u;
}

// ================= fused convert (5 tensors) + gather/normalize =================
__global__ void prep_kernel(const float* __restrict__ xh, const float* __restrict__ xt,
                            const float* __restrict__ Wh, const float* __restrict__ Wv,
                            const float* __restrict__ Wo,
                            const float* __restrict__ colh, const float* __restrict__ colt,
                            const int* __restrict__ ids)
{
    const int t = blockIdx.y;
    if (t < 5) {
        const int n4 = (t < 2) ? (BT * 512 / 4) : (512 * 512 / 4);
        const int i = blockIdx.x * blockDim.x + threadIdx.x;
        if (i >= n4) return;
        const float* in; bf16 *hi, *lo;
        switch (t) {
            case 0: in = xh; hi = g_xhH; lo = g_xhL; break;
            case 1: in = xt; hi = g_xtH; lo = g_xtL; break;
            case 2: in = Wh; hi = g_WhH; lo = g_WhL; break;
            case 3: in = Wv; hi = g_WvH; lo = g_WvL; break;
            default: in = Wo; hi = g_WoH; lo = g_WoL; break;
        }
        float4 v = ((const float4*)in)[i];
        uint2 h, l; split4(v, h, l);
        ((uint2*)hi)[i] = h;
        ((uint2*)lo)[i] = l;
        return;
    }
    // t == 5: gather + L2 normalize (warp per row)
    const int w = (blockIdx.x * blockDim.x + threadIdx.x) >> 5;
    const int lane = threadIdx.x & 31;
    if (w >= BHT) return;
    const int q = w % T;
    const int bh = w / T;
    const int h = bh & 7, b = bh >> 3;
    const int srow = (q == 0) ? 0 : (ids[b * (T - 1) + (q - 1)] + 1);
    {
        float v = (lane < 22) ? colh[((size_t)h * NCOLS + srow) * 22 + lane] : 0.f;
        float ss = v * v;
#pragma unroll
        for (int o = 16; o; o >>= 1) ss += __shfl_xor_sync(0xffffffffu, ss, o);
        float nv = (lane < 22) ? v / sqrtf(ss) : 0.f;
        if (lane < 24) g_chf[(size_t)w * 24 + lane] = nv;
        bf16 hi = __float2bfloat16_rn(nv);
        g_chH[(size_t)w * 32 + lane] = hi;
        g_chL[(size_t)w * 32 + lane] = __float2bfloat16_rn(nv - __bfloat162float(hi));
    }
    {
        float v = (lane < 22) ? colt[((size_t)h * NCOLS + srow) * 22 + lane] : 0.f;
        float ss = v * v;
#pragma unroll
        for (int o = 16; o; o >>= 1) ss += __shfl_xor_sync(0xffffffffu, ss, o);
        float nv = (lane < 22) ? v / sqrtf(ss) : 0.f;
        if (lane < 24) g_ctf[(size_t)w * 24 + lane] = nv;
        bf16 hi = __float2bfloat16_rn(nv);
        g_ctH[(size_t)w * 32 + lane] = hi;
        g_ctL[(size_t)w * 32 + lane] = __float2bfloat16_rn(nv - __bfloat162float(hi));
    }
}

// ================= batched pipelined HMMA GEMM (2 CTAs/SM) =================
struct Job {
    const bf16 *AH, *AL, *WH, *WL;
    const float *bias, *scale;
    float* Cf;
    bf16 *CH, *CL;
};
struct Jobs3 { Job j[3]; };

constexpr uint32_t GEMM_SMEM = 2 * 4 * 128 * 40 * 2;   // 81920
constexpr uint32_t G_PL = 128 * 40 * 2;
constexpr uint32_t G_ST = 4 * G_PL;

__global__ __launch_bounds__(256, 2) void gemm_batched(Jobs3 jobs, int M)
{
    extern __shared__ char dsm[];
    const Job J = jobs.j[blockIdx.z];
    const uint32_t sm = smem_addr(dsm);
    const int tid = threadIdx.x;
    const int wid = tid >> 5, lane = tid & 31;
    const int wm = wid & 3, wn = wid >> 2;
    const int m0 = blockIdx.y * 128, n0 = blockIdx.x * 128;
    const int a_r = lane & 15, a_c = (lane >> 4) * 8;
    const int b_r = lane & 7,  b_c = (lane >> 3) * 8;

    float acc[2][8][4];
#pragma unroll
    for (int mi = 0; mi < 2; mi++)
#pragma unroll
        for (int ni = 0; ni < 8; ni++)
#pragma unroll
            for (int r = 0; r < 4; r++) acc[mi][ni][r] = 0.f;

    const int r0 = tid >> 2, c0 = (tid & 3) * 8;
    const int r1 = (tid + 256) >> 2, c1 = ((tid + 256) & 3) * 8;

    auto load_stage = [&](int st, int chunk) {
        const int k0 = chunk * 32;
        const uint32_t base = sm + st * G_ST;
#pragma unroll
        for (int i = 0; i < 2; i++) {
            const int row = i ? r1 : r0, cs = i ? c1 : c0;
            const int gr = m0 + row;
            const int grc = (gr < M) ? gr : (M - 1);
            const int ab = (gr < M) ? 16 : 0;
            const size_t aoff = (size_t)grc * 512 + k0 + cs;
            const size_t woff = (size_t)(n0 + row) * 512 + k0 + cs;
            const uint32_t so = (row * 40 + cs) * 2;
            cp16(base + so,            J.AH + aoff, ab);
            cp16(base + G_PL + so,     J.AL + aoff, ab);
            cp16(base + 2 * G_PL + so, J.WH + woff, 16);
            cp16(base + 3 * G_PL + so, J.WL + woff, 16);
        }
    };

    load_stage(0, 0);
    CP_COMMIT();

    for (int chunk = 0; chunk < 16; chunk++) {
        const int st = chunk & 1;
        if (chunk + 1 < 16) {
            load_stage(st ^ 1, chunk + 1);
            CP_COMMIT();
            CP_WAIT(1);
        } else {
            CP_WAIT(0);
        }
        __syncthreads();

        bf16 (*AsH)[40] = (bf16(*)[40])(dsm + st * G_ST);
        bf16 (*AsL)[40] = (bf16(*)[40])(dsm + st * G_ST + G_PL);
        bf16 (*BsH)[40] = (bf16(*)[40])(dsm + st * G_ST + 2 * G_PL);
        bf16 (*BsL)[40] = (bf16(*)[40])(dsm + st * G_ST + 3 * G_PL);

        uint32_t ah[2][2][4], al[2][2][4];
#pragma unroll
        for (int mi = 0; mi < 2; mi++) {
            const int r = wm * 32 + mi * 16 + a_r;
#pragma unroll
            for (int ks = 0; ks < 2; ks++) {
                const int c = ks * 16 + a_c;
                ldsm_x4(ah[mi][ks], smem_addr(&AsH[r][c]));
                ldsm_x4(al[mi][ks], smem_addr(&AsL[r][c]));
            }
        }
#pragma unroll
        for (int ni = 0; ni < 8; ni++) {
            const int r = wn * 64 + ni * 8 + b_r;
            uint32_t bh4[4], bl4[4];
            ldsm_x4(bh4, smem_addr(&BsH[r][b_c]));
            ldsm_x4(bl4, smem_addr(&BsL[r][b_c]));
#pragma unroll
            for (int mi = 0; mi < 2; mi++) {
#pragma unroll
                for (int ks = 0; ks < 2; ks++) {
                    mma_bf16(acc[mi][ni], ah[mi][ks], bh4[2 * ks], bh4[2 * ks + 1]);
                    mma_bf16(acc[mi][ni], ah[mi][ks], bl4[2 * ks], bl4[2 * ks + 1]);
                    mma_bf16(acc[mi][ni], al[mi][ks], bh4[2 * ks], bh4[2 * ks + 1]);
                }
            }
        }
        __syncthreads();
    }

    const int tr = lane >> 2, tc = (lane & 3) * 2;
#pragma unroll
    for (int mi = 0; mi < 2; mi++) {
#pragma unroll
        for (int ni = 0; ni < 8; ni++) {
            const int n = n0 + wn * 64 + ni * 8 + tc;
            const float b0 = J.bias[n], b1 = J.bias[n + 1];
            float s0 = 1.f, s1 = 1.f;
            if (J.scale) { s0 = J.scale[n]; s1 = J.scale[n + 1]; }
#pragma unroll
            for (int half = 0; half < 2; half++) {
                const int m = m0 + wm * 32 + mi * 16 + tr + half * 8;
                if (m >= M) continue;
                const float x = (acc[mi][ni][half * 2 + 0] + b0) * s0;
                const float y = (acc[mi][ni][half * 2 + 1] + b1) * s1;
                const size_t off = (size_t)m * 512 + n;
                if (J.Cf) *(float2*)(J.Cf + off) = make_float2(x, y);
                if (J.CH) {
                    uint32_t hi, lo; split2(x, y, hi, lo);
                    *(uint32_t*)(J.CH + off) = hi;
                    *(uint32_t*)(J.CL + off) = lo;
                }
            }
        }
    }
}

// ================= logits: 64q x 64k tile, 3 CTAs/SM (known good) =================
constexpr uint32_t LOGITS_SMEM = 36864;
constexpr float RESCUE_BAND = 1e-4f;

__global__ __launch_bounds__(256, 3) void logits_hmma(const float* __restrict__ bias,
                                                      float* __restrict__ FR)
{
    extern __shared__ char dsm[];
    const uint32_t sm = smem_addr(dsm);
    const int tid = threadIdx.x;
    const int wid = tid >> 5, lane = tid & 31;
    const int wm = wid & 1, wn = wid >> 1;           // 2 m-warps x 4 n-warps
    const int bh = blockIdx.z, b = bh >> 3, h = bh & 7;
    const int q0 = blockIdx.y * 64, k0 = blockIdx.x * 64;
    const int a_r = lane & 15, a_c = (lane >> 4) * 8;
    const int b_r = lane & 7,  b_c = (lane >> 3) * 8;
    const int tr = lane >> 2,  tc = (lane & 3) * 2;
    const float bias0 = bias[0];

    // ---- load phase A ----
    {
        const int row = tid >> 2, cs = (tid & 3) * 8;
        const int q = q0 + row, k = k0 + row;
        const int qc = (q < T) ? q : (T - 1), kc = (k < T) ? k : (T - 1);
        const int qb = (q < T) ? 16 : 0, kb = (k < T) ? 16 : 0;
        const size_t qoff = ((size_t)bh * T + qc) * 32 + cs;
        const size_t koff = ((size_t)bh * T + kc) * 32 + cs;
        const uint32_t so = row * 80 + cs * 2;
        cp16(sm + so,         g_chH + qoff, qb);
        cp16(sm + 5120 + so,  g_chL + qoff, qb);
        cp16(sm + 10240 + so, g_ctH + koff, kb);
        cp16(sm + 15360 + so, g_ctL + koff, kb);
    }
    CP_COMMIT();
    CP_WAIT(0);
    __syncthreads();

    float acc[2][2][4];
#pragma unroll
    for (int mi = 0; mi < 2; mi++)
#pragma unroll
        for (int ni = 0; ni < 2; ni++)
#pragma unroll
            for (int r = 0; r < 4; r++) acc[mi][ni][r] = 0.f;

    // ---- phase A ----
    {
        bf16 (*QH)[40] = (bf16(*)[40])(dsm);
        bf16 (*QL)[40] = (bf16(*)[40])(dsm + 5120);
        bf16 (*KH)[40] = (bf16(*)[40])(dsm + 10240);
        bf16 (*KL)[40] = (bf16(*)[40])(dsm + 15360);
        uint32_t ah[2][2][4], al[2][2][4];
#pragma unroll
        for (int mi = 0; mi < 2; mi++) {
            const int r = wm * 32 + mi * 16 + a_r;
#pragma unroll
            for (int ks = 0; ks < 2; ks++) {
                ldsm_x4(ah[mi][ks], smem_addr(&QH[r][ks * 16 + a_c]));
                ldsm_x4(al[mi][ks], smem_addr(&QL[r][ks * 16 + a_c]));
            }
        }
#pragma unroll
        for (int ni = 0; ni < 2; ni++) {
            const int r = wn * 16 + ni * 8 + b_r;
            uint32_t bh4[4], bl4[4];
            ldsm_x4(bh4, smem_addr(&KH[r][b_c]));
            ldsm_x4(bl4, smem_addr(&KL[r][b_c]));
#pragma unroll
            for (int mi = 0; mi < 2; mi++) {
#pragma unroll
                for (int ks = 0; ks < 2; ks++) {
                    mma_bf16(acc[mi][ni], ah[mi][ks], bh4[2 * ks], bh4[2 * ks + 1]);
                    mma_bf16(acc[mi][ni], ah[mi][ks], bl4[2 * ks], bl4[2 * ks + 1]);
                    mma_bf16(acc[mi][ni], al[mi][ks], bh4[2 * ks], bh4[2 * ks + 1]);
                }
            }
        }
    }
    __syncthreads();

    // ---- issue phase B loads ----
#pragma unroll
    for (int i = 0; i < 2; i++) {
        const int s = tid + 256 * i;
        const int row = s >> 3, cs = (s & 7) * 8;
        const int q = q0 + row, k = k0 + row;
        const int qc = (q < T) ? q : (T - 1), kc = (k < T) ? k : (T - 1);
        const int qb = (q < T) ? 16 : 0, kb = (k < T) ? 16 : 0;
        const size_t xoff = ((size_t)(b * T + qc)) * 512 + h * 64 + cs;
        const size_t yoff = ((size_t)(b * T + kc)) * 512 + h * 64 + cs;
        const uint32_t so = row * 144 + cs * 2;
        cp16(sm + so,         g_fhH + xoff, qb);
        cp16(sm + 9216 + so,  g_fhL + xoff, qb);
        cp16(sm + 18432 + so, g_ftH + yoff, kb);
        cp16(sm + 27648 + so, g_ftL + yoff, kb);
    }
    CP_COMMIT();

    // ---- masks ----
    uint32_t adjm = 0u, unc = 0u;
#pragma unroll
    for (int mi = 0; mi < 2; mi++)
#pragma unroll
        for (int ni = 0; ni < 2; ni++)
#pragma unroll
            for (int r = 0; r < 4; r++) {
                const int q = q0 + wm * 32 + mi * 16 + tr + (r >> 1) * 8;
                const int k = k0 + wn * 16 + ni * 8 + tc + (r & 1);
                const bool valid = (q < T) && (k < T) && (k != 0) && (k != q);
                if (valid) {
                    const float ts = acc[mi][ni][r] + bias0;
                    const int idx = (mi * 2 + ni) * 4 + r;
                    if (fabsf(ts) < RESCUE_BAND) unc |= 1u << idx;
                    if (ts > 0.f)                adjm |= 1u << idx;
                }
            }

    // ---- phase B ----
#pragma unroll
    for (int mi = 0; mi < 2; mi++)
#pragma unroll
        for (int ni = 0; ni < 2; ni++)
#pragma unroll
            for (int r = 0; r < 4; r++) acc[mi][ni][r] = 0.f;

    CP_WAIT(0);
    __syncthreads();
    {
        bf16 (*XH)[72] = (bf16(*)[72])(dsm);
        bf16 (*XL)[72] = (bf16(*)[72])(dsm + 9216);
        bf16 (*YH)[72] = (bf16(*)[72])(dsm + 18432);
        bf16 (*YL)[72] = (bf16(*)[72])(dsm + 27648);
#pragma unroll
        for (int kk = 0; kk < 64; kk += 32) {
            uint32_t ah[2][2][4], al[2][2][4];
#pragma unroll
            for (int mi = 0; mi < 2; mi++) {
                const int r = wm * 32 + mi * 16 + a_r;
#pragma unroll
                for (int ks = 0; ks < 2; ks++) {
                    const int c = kk + ks * 16 + a_c;
                    ldsm_x4(ah[mi][ks], smem_addr(&XH[r][c]));
                    ldsm_x4(al[mi][ks], smem_addr(&XL[r][c]));
                }
            }
#pragma unroll
            for (int ni = 0; ni < 2; ni++) {
                const int r = wn * 16 + ni * 8 + b_r;
                uint32_t bh4[4], bl4[4];
                ldsm_x4(bh4, smem_addr(&YH[r][kk + b_c]));
                ldsm_x4(bl4, smem_addr(&YL[r][kk + b_c]));
#pragma unroll
                for (int mi = 0; mi < 2; mi++) {
#pragma unroll
                    for (int ks = 0; ks < 2; ks++) {
                        mma_bf16(acc[mi][ni], ah[mi][ks], bh4[2 * ks], bh4[2 * ks + 1]);
                        mma_bf16(acc[mi][ni], ah[mi][ks], bl4[2 * ks], bl4[2 * ks + 1]);
                        mma_bf16(acc[mi][ni], al[mi][ks], bh4[2 * ks], bh4[2 * ks + 1]);
                    }
                }
            }
        }
    }
    __syncthreads();

    // ---- stage masked logits into smem tile ----
    {
        float (*stg)[68] = (float(*)[68])dsm;
#pragma unroll
        for (int mi = 0; mi < 2; mi++) {
#pragma unroll
            for (int ni = 0; ni < 2; ni++) {
#pragma unroll
                for (int r = 0; r < 4; r++) {
                    const int ql = wm * 32 + mi * 16 + tr + (r >> 1) * 8;
                    const int kl = wn * 16 + ni * 8 + tc + (r & 1);
                    const int idx = (mi * 2 + ni) * 4 + r;
                    bool abit;
                    if ((unc >> idx) & 1u) {
                        const float* cq = g_chf + ((size_t)bh * T + q0 + ql) * 24;
                        const float* ck = g_ctf + ((size_t)bh * T + k0 + kl) * 24;
                        float d = 0.f;
#pragma unroll
                        for (int c = 0; c < 22; c++) d = fmaf(cq[c], ck[c], d);
                        abit = (d + bias0 > 0.f);
                    } else {
                        abit = (adjm >> idx) & 1u;
                    }
                    float v = acc[mi][ni][r] * 0.125f;
                    if (!abit) v -= 10000.0f;
                    stg[ql][kl] = v;
                }
            }
        }
    }
    __syncthreads();

    // ---- coalesced FR store ----
    {
        float (*stg)[68] = (float(*)[68])dsm;
        const int kmax = T - k0;
#pragma unroll
        for (int r = 0; r < 8; r++) {
            const int row = wid * 8 + r;
            const int q = q0 + row;
            if (q >= T) break;
            float* fr = FR + ((size_t)bh * T + q) * T + k0;
#pragma unroll
            for (int j = 0; j < 2; j++) {
                const int col = lane + 32 * j;
                if (col < kmax) fr[col] = stg[row][col];
            }
        }
    }
}

// ================= softmax: single-pass (validated in R14) =================
__global__ __launch_bounds__(256) void softmax_kernel(float* __restrict__ FR)
{
    __shared__ float sred[8];
    const int tid = threadIdx.x;
    const int wid = tid >> 5, lane = tid & 31;
    float* base = FR + (size_t)blockIdx.x * T;
    bf16* ph = g_pH + (size_t)blockIdx.x * TP;
    bf16* pl = g_pL + (size_t)blockIdx.x * TP;

    float e[4];
    int n = 0;
    float s = 0.f;
    for (int i = tid; i < T; i += 256) { e[n] = __expf(base[i]); s += e[n]; n++; }
#pragma unroll
    for (int o = 16; o; o >>= 1) s += __shfl_xor_sync(0xffffffffu, s, o);
    if (lane == 0) sred[wid] = s;
    __syncthreads();
    s = 0.f;
#pragma unroll
    for (int w = 0; w < 8; w++) s += sred[w];
    const float inv = 1.0f / s;
    n = 0;
    for (int i = tid; i < T; i += 256) {
        const float p = e[n] * inv;
        base[i] = p;
        const bf16 hi = __float2bfloat16_rn(p);
        ph[i] = hi;
        pl[i] = __float2bfloat16_rn(p - __bfloat162float(hi));
        n++;
    }
}

// ================= pipelined AV (R10/R13, no launch-bounds cap) =================
constexpr uint32_t AV_PP = 128 * 40 * 2;
constexpr uint32_t AV_VP = 32 * 72 * 2;
constexpr uint32_t AV_ST = 2 * AV_PP + 2 * AV_VP;
constexpr uint32_t AV_SMEM = 2 * AV_ST;

__global__ __launch_bounds__(256) void av_hmma()
{
    extern __shared__ char dsm[];
    const uint32_t sm = smem_addr(dsm);
    const int tid = threadIdx.x;
    const int wid = tid >> 5, lane = tid & 31;
    const int wm = wid & 3, wn = wid >> 2;
    const int bh = blockIdx.y, b = bh >> 3, h = bh & 7;
    const int q0 = blockIdx.x * 128;
    const int a_r = lane & 15, a_c = (lane >> 4) * 8;
    const int tr = lane >> 2, tc = (lane & 3) * 2;

    float acc[2][4][4];
#pragma unroll
    for (int mi = 0; mi < 2; mi++)
#pragma unroll
        for (int ni = 0; ni < 4; ni++)
#pragma unroll
            for (int r = 0; r < 4; r++) acc[mi][ni][r] = 0.f;

    const int pr0 = tid >> 2, pc0 = (tid & 3) * 8;
    const int pr1 = (tid + 256) >> 2, pc1 = ((tid + 256) & 3) * 8;
    const int vr = tid >> 3, vc = (tid & 7) * 8;

    auto load_stage = [&](int st, int k0) {
        const uint32_t base = sm + st * AV_ST;
#pragma unroll
        for (int i = 0; i < 2; i++) {
            const int row = i ? pr1 : pr0, c8 = i ? pc1 : pc0;
            const int q = q0 + row;
            const int qc = (q < T) ? q : (T - 1);
            const int pb = (q < T) ? 16 : 0;
            const size_t off = ((size_t)bh * T + qc) * TP + k0 + c8;
            const uint32_t so = (row * 40 + c8) * 2;
            cp16(base + so,         g_pH + off, pb);
            cp16(base + AV_PP + so, g_pL + off, pb);
        }
        {
            const int kv = k0 + vr;
            const int kc = (kv < T) ? kv : (T - 1);
            const int vb = (kv < T) ? 16 : 0;
            const size_t off = ((size_t)(b * T + kc)) * 512 + h * 64 + vc;
            const uint32_t so = (vr * 72 + vc) * 2;
            cp16(base + 2 * AV_PP + so,         g_fvH + off, vb);
            cp16(base + 2 * AV_PP + AV_VP + so, g_fvL + off, vb);
        }
    };

    load_stage(0, 0);
    CP_COMMIT();

    constexpr int NCHUNK = TP / 32;
    for (int chunk = 0; chunk < NCHUNK; chunk++) {
        const int st = chunk & 1;
        if (chunk + 1 < NCHUNK) {
            load_stage(st ^ 1, (chunk + 1) * 32);
            CP_COMMIT();
            CP_WAIT(1);
        } else {
            CP_WAIT(0);
        }
        __syncthreads();

        bf16 (*PsH)[40] = (bf16(*)[40])(dsm + st * AV_ST);
        bf16 (*PsL)[40] = (bf16(*)[40])(dsm + st * AV_ST + AV_PP);
        bf16 (*VsH)[72] = (bf16(*)[72])(dsm + st * AV_ST + 2 * AV_PP);
        bf16 (*VsL)[72] = (bf16(*)[72])(dsm + st * AV_ST + 2 * AV_PP + AV_VP);

        uint32_t ah[2][2][4], al[2][2][4];
#pragma unroll
        for (int mi = 0; mi < 2; mi++) {
            const int r = wm * 32 + mi * 16 + a_r;
#pragma unroll
            for (int ks = 0; ks < 2; ks++) {
                const int c = ks * 16 + a_c;
                ldsm_x4(ah[mi][ks], smem_addr(&PsH[r][c]));
                ldsm_x4(al[mi][ks], smem_addr(&PsL[r][c]));
            }
        }
#pragma unroll
        for (int ni = 0; ni < 4; ni++) {
            const int nb = wn * 32 + ni * 8;
            uint32_t bh4[4], bl4[4];
            ldsm_x4_t(bh4, smem_addr(&VsH[lane][nb]));
            ldsm_x4_t(bl4, smem_addr(&VsL[lane][nb]));
#pragma unroll
            for (int mi = 0; mi < 2; mi++) {
#pragma unroll
                for (int ks = 0; ks < 2; ks++) {
                    mma_bf16(acc[mi][ni], ah[mi][ks], bh4[2 * ks], bh4[2 * ks + 1]);
                    mma_bf16(acc[mi][ni], ah[mi][ks], bl4[2 * ks], bl4[2 * ks + 1]);
                    mma_bf16(acc[mi][ni], al[mi][ks], bh4[2 * ks], bh4[2 * ks + 1]);
                }
            }
        }
        __syncthreads();
    }

#pragma unroll
    for (int mi = 0; mi < 2; mi++) {
#pragma unroll
        for (int ni = 0; ni < 4; ni++) {
            const int n = wn * 32 + ni * 8 + tc;
#pragma unroll
            for (int half = 0; half < 2; half++) {
                const int q = q0 + wm * 32 + mi * 16 + tr + half * 8;
                if (q >= T) continue;
                const float x = acc[mi][ni][half * 2 + 0];
                const float y = acc[mi][ni][half * 2 + 1];
                uint32_t hi, lo; split2(x, y, hi, lo);
                const size_t off = ((size_t)(b * T + q)) * 512 + h * 64 + n;
                *(uint32_t*)(g_xaH + off) = hi;
                *(uint32_t*)(g_xaL + off) = lo;
            }
        }
    }
}

// ---------------- launcher ----------------
extern "C" void kernel_launch(void* const* d_in, const int* in_sizes, int n_in,
                              void* d_out, int out_size)
{
    const float* x_head = (const float*)d_in[0];
    const float* x_tail = (const float*)d_in[1];
    const int*   ids    = (const int*)  d_in[2];
    const float* Wh     = (const float*)d_in[3];
    const float* bh     = (const float*)d_in[4];
    const float* Wv     = (const float*)d_in[5];
    const float* bv     = (const float*)d_in[6];
    const float* Wo     = (const float*)d_in[7];
    const float* bo     = (const float*)d_in[8];
    const float* rel    = (const float*)d_in[9];
    const float* colh   = (const float*)d_in[10];
    const float* colt   = (const float*)d_in[11];
    const float* bias   = (const float*)d_in[12];

    float* out = (float*)d_out;
    float* FR  = out + X_ELEMS;

    bf16 *xhH, *xhL, *xtH, *xtL, *WhH, *WhL, *WvH, *WvL, *WoH, *WoL;
    bf16 *fhH, *fhL, *ftH, *ftL, *fvH, *fvL, *xaH, *xaL;
    cudaGetSymbolAddress((void**)&xhH, g_xhH); cudaGetSymbolAddress((void**)&xhL, g_xhL);
    cudaGetSymbolAddress((void**)&xtH, g_xtH); cudaGetSymbolAddress((void**)&xtL, g_xtL);
    cudaGetSymbolAddress((void**)&WhH, g_WhH); cudaGetSymbolAddress((void**)&WhL, g_WhL);
    cudaGetSymbolAddress((void**)&WvH, g_WvH); cudaGetSymbolAddress((void**)&WvL, g_WvL);
    cudaGetSymbolAddress((void**)&WoH, g_WoH); cudaGetSymbolAddress((void**)&WoL, g_WoL);
    cudaGetSymbolAddress((void**)&fhH, g_fhH); cudaGetSymbolAddress((void**)&fhL, g_fhL);
    cudaGetSymbolAddress((void**)&ftH, g_ftH); cudaGetSymbolAddress((void**)&ftL, g_ftL);
    cudaGetSymbolAddress((void**)&fvH, g_fvH); cudaGetSymbolAddress((void**)&fvL, g_fvL);
    cudaGetSymbolAddress((void**)&xaH, g_xaH); cudaGetSymbolAddress((void**)&xaL, g_xaL);

    cudaFuncSetAttribute(gemm_batched, cudaFuncAttributeMaxDynamicSharedMemorySize, GEMM_SMEM);
    cudaFuncSetAttribute(logits_hmma, cudaFuncAttributeMaxDynamicSharedMemorySize, LOGITS_SMEM);
    cudaFuncSetAttribute(av_hmma, cudaFuncAttributeMaxDynamicSharedMemorySize, AV_SMEM);

    // launch 1: fused convert + gather
    prep_kernel<<<dim3(6152, 6), 256>>>(x_head, x_tail, Wh, Wv, Wo, colh, colt, ids);
    // launch 2: projections
    Jobs3 pj;
    pj.j[0] = { xhH, xhL, WhH, WhL, bh, rel,     nullptr, fhH, fhL };
    pj.j[1] = { xtH, xtL, WhH, WhL, bh, nullptr, nullptr, ftH, ftL };
    pj.j[2] = { xtH, xtL, WvH, WvL, bv, nullptr, nullptr, fvH, fvL };
    gemm_batched<<<dim3(4, (BT + 127) / 128, 3), 256, GEMM_SMEM>>>(pj, BT);
    // launch 3: logits (64q x 64k tiles)
    dim3 gLog((T + 63) / 64, (T + 63) / 64, B * H);   // (13, 13, 64)
    logits_hmma<<<gLog, 256, LOGITS_SMEM>>>(bias, FR);
    // launch 4: softmax (single-pass)
    softmax_kernel<<<B * H * T, 256>>>(FR);
    // launch 5: AV
    dim3 gAV((T + 127) / 128, B * H);
    av_hmma<<<gAV, 256, AV_SMEM>>>();
    // launch 6: output projection
    Jobs3 oj;
    oj.j[0] = { xaH, xaL, WoH, WoL, bo, nullptr, out, nullptr, nullptr };
    oj.j[1] = oj.j[0];
    oj.j[2] = oj.j[0];
    gemm_batched<<<dim3(4, (BT + 127) / 128, 1), 256, GEMM_SMEM>>>(oj, BT);
}

// round 16
// speedup vs baseline: 1.0364x; 1.0176x over previous
#include <cuda_runtime.h>
#include <cuda_bf16.h>
#include <math.h>
#include <stdint.h>

// ---------------- problem constants ----------------
constexpr int B = 8;
constexpr int T = 769;
constexpr int H = 8;
constexpr int NCOLS = 2048;
constexpr int BT = B * T;            // 6152
constexpr int BHT = B * H * T;       // 49216
constexpr int TP = 800;              // padded k-extent for P planes
constexpr long long X_ELEMS = (long long)BT * 512;

typedef __nv_bfloat16 bf16;

// ---------------- scratch (device globals; zero-initialized) ----------------
__device__ bf16 g_xhH[BT * 512], g_xhL[BT * 512];
__device__ bf16 g_xtH[BT * 512], g_xtL[BT * 512];
__device__ bf16 g_WhH[512 * 512], g_WhL[512 * 512];
__device__ bf16 g_WvH[512 * 512], g_WvL[512 * 512];
__device__ bf16 g_WoH[512 * 512], g_WoL[512 * 512];
__device__ bf16 g_fhH[BT * 512], g_fhL[BT * 512];
__device__ bf16 g_ftH[BT * 512], g_ftL[BT * 512];
__device__ bf16 g_fvH[BT * 512], g_fvL[BT * 512];
__device__ bf16 g_xaH[BT * 512], g_xaL[BT * 512];
__device__ bf16 g_chH[BHT * 32], g_chL[BHT * 32];
__device__ bf16 g_ctH[BHT * 32], g_ctL[BHT * 32];
__device__ float g_chf[BHT * 24], g_ctf[BHT * 24];
__device__ bf16 g_pH[(size_t)BHT * TP], g_pL[(size_t)BHT * TP];

// ================= helpers =================
__device__ __forceinline__ void ldsm_x4(uint32_t* r, uint32_t addr) {
    asm volatile("ldmatrix.sync.aligned.m8n8.x4.shared.b16 {%0,%1,%2,%3}, [%4];"
                 : "=r"(r[0]), "=r"(r[1]), "=r"(r[2]), "=r"(r[3]) : "r"(addr));
}
__device__ __forceinline__ void ldsm_x4_t(uint32_t* r, uint32_t addr) {
    asm volatile("ldmatrix.sync.aligned.m8n8.x4.trans.shared.b16 {%0,%1,%2,%3}, [%4];"
                 : "=r"(r[0]), "=r"(r[1]), "=r"(r[2]), "=r"(r[3]) : "r"(addr));
}
__device__ __forceinline__ void mma_bf16(float* c, const uint32_t* a, uint32_t b0, uint32_t b1) {
    asm volatile("mma.sync.aligned.m16n8k16.row.col.f32.bf16.bf16.f32 "
                 "{%0,%1,%2,%3}, {%4,%5,%6,%7}, {%8,%9}, {%0,%1,%2,%3};"
                 : "+f"(c[0]), "+f"(c[1]), "+f"(c[2]), "+f"(c[3])
                 : "r"(a[0]), "r"(a[1]), "r"(a[2]), "r"(a[3]), "r"(b0), "r"(b1));
}
__device__ __forceinline__ uint32_t smem_addr(const void* p) {
    return (uint32_t)__cvta_generic_to_shared(p);
}
__device__ __forceinline__ void cp16(uint32_t dst, const void* src, int bytes) {
    asm volatile("cp.async.cg.shared.global [%0], [%1], 16, %2;"
                 :: "r"(dst), "l"(src), "r"(bytes));
}
#define CP_COMMIT() asm volatile("cp.async.commit_group;")
#define CP_WAIT(n)  asm volatile("cp.async.wait_group %0;" :: "n"(n))

__device__ __forceinline__ void split4(float4 v, uint2& hi, uint2& lo) {
    float f[4] = {v.x, v.y, v.z, v.w};
    float fh[4], fl[4];
#pragma unroll
    for (int j = 0; j < 4; j++) {
        fh[j] = __bfloat162float(__float2bfloat16_rn(f[j]));
        fl[j] = f[j] - fh[j];
    }
    union { __nv_bfloat162 h2[2]; uint2 u; } a, b;
    a.h2[0] = __floats2bfloat162_rn(fh[0], fh[1]);
    a.h2[1] = __floats2bfloat162_rn(fh[2], fh[3]);
    b.h2[0] = __floats2bfloat162_rn(fl[0], fl[1]);
    b.h2[1] = __floats2bfloat162_rn(fl[2], fl[3]);
    hi = a.u; lo = b.u;
}
__device__ __forceinline__ void split2(float x, float y, uint32_t& hi, uint32_t& lo) {
    float hx = __bfloat162float(__float2bfloat16_rn(x));
    float hy = __bfloat162float(__float2bfloat16_rn(y));
    union { __nv_bfloat162 h2; uint32_t u; } a, b;
    a.h2 = __floats2bfloat162_rn(hx, hy);
    b.h2 = __floats2bfloat162_rn(x - hx, y - hy);
    hi = a.u; lo = b.u;
}

// ================= prep: 1D right-sized grid (converts + gather) =================
// blocks: [0,3076) xh | [3076,6152) xt | [6152,6408) Wh | [6408,6664) Wv
//         [6664,6920) Wo | [6920,13072) gather
constexpr int PREP_BLOCKS = 13072;

__global__ void prep_kernel(const float* __restrict__ xh, const float* __restrict__ xt,
                            const float* __restrict__ Wh, const float* __restrict__ Wv,
                            const float* __restrict__ Wo,
                            const float* __restrict__ colh, const float* __restrict__ colt,
                            const int* __restrict__ ids)
{
    const int bx = blockIdx.x;
    const int tid = threadIdx.x;
    if (bx < 6152) {
        const float* in; bf16 *hi, *lo;
        int i;
        if (bx < 3076) { in = xh; hi = g_xhH; lo = g_xhL; i = bx * 256 + tid; }
        else           { in = xt; hi = g_xtH; lo = g_xtL; i = (bx - 3076) * 256 + tid; }
        float4 v = ((const float4*)in)[i];
        uint2 h, l; split4(v, h, l);
        ((uint2*)hi)[i] = h;
        ((uint2*)lo)[i] = l;
        return;
    }
    if (bx < 6920) {
        const int s = bx - 6152;
        const float* in; bf16 *hi, *lo;
        int i;
        if (s < 256)      { in = Wh; hi = g_WhH; lo = g_WhL; i = s * 256 + tid; }
        else if (s < 512) { in = Wv; hi = g_WvH; lo = g_WvL; i = (s - 256) * 256 + tid; }
        else              { in = Wo; hi = g_WoH; lo = g_WoL; i = (s - 512) * 256 + tid; }
        float4 v = ((const float4*)in)[i];
        uint2 h, l; split4(v, h, l);
        ((uint2*)hi)[i] = h;
        ((uint2*)lo)[i] = l;
        return;
    }
    // gather + L2 normalize (warp per row); 6152 blocks x 8 warps = 49216 rows
    const int w = (bx - 6920) * 8 + (tid >> 5);
    const int lane = tid & 31;
    const int q = w % T;
    const int bh = w / T;
    const int h = bh & 7, b = bh >> 3;
    const int srow = (q == 0) ? 0 : (ids[b * (T - 1) + (q - 1)] + 1);
    {
        float v = (lane < 22) ? colh[((size_t)h * NCOLS + srow) * 22 + lane] : 0.f;
        float ss = v * v;
#pragma unroll
        for (int o = 16; o; o >>= 1) ss += __shfl_xor_sync(0xffffffffu, ss, o);
        float nv = (lane < 22) ? v / sqrtf(ss) : 0.f;
        if (lane < 24) g_chf[(size_t)w * 24 + lane] = nv;
        bf16 hi = __float2bfloat16_rn(nv);
        g_chH[(size_t)w * 32 + lane] = hi;
        g_chL[(size_t)w * 32 + lane] = __float2bfloat16_rn(nv - __bfloat162float(hi));
    }
    {
        float v = (lane < 22) ? colt[((size_t)h * NCOLS + srow) * 22 + lane] : 0.f;
        float ss = v * v;
#pragma unroll
        for (int o = 16; o; o >>= 1) ss += __shfl_xor_sync(0xffffffffu, ss, o);
        float nv = (lane < 22) ? v / sqrtf(ss) : 0.f;
        if (lane < 24) g_ctf[(size_t)w * 24 + lane] = nv;
        bf16 hi = __float2bfloat16_rn(nv);
        g_ctH[(size_t)w * 32 + lane] = hi;
        g_ctL[(size_t)w * 32 + lane] = __float2bfloat16_rn(nv - __bfloat162float(hi));
    }
}

// ================= batched pipelined HMMA GEMM (2 CTAs/SM; known good) =================
struct Job {
    const bf16 *AH, *AL, *WH, *WL;
    const float *bias, *scale;
    float* Cf;
    bf16 *CH, *CL;
};
struct Jobs3 { Job j[3]; };

constexpr uint32_t GEMM_SMEM = 2 * 4 * 128 * 40 * 2;   // 81920
constexpr uint32_t G_PL = 128 * 40 * 2;
constexpr uint32_t G_ST = 4 * G_PL;

__global__ __launch_bounds__(256, 2) void gemm_batched(Jobs3 jobs, int M)
{
    extern __shared__ char dsm[];
    const Job J = jobs.j[blockIdx.z];
    const uint32_t sm = smem_addr(dsm);
    const int tid = threadIdx.x;
    const int wid = tid >> 5, lane = tid & 31;
    const int wm = wid & 3, wn = wid >> 2;
    const int m0 = blockIdx.y * 128, n0 = blockIdx.x * 128;
    const int a_r = lane & 15, a_c = (lane >> 4) * 8;
    const int b_r = lane & 7,  b_c = (lane >> 3) * 8;

    float acc[2][8][4];
#pragma unroll
    for (int mi = 0; mi < 2; mi++)
#pragma unroll
        for (int ni = 0; ni < 8; ni++)
#pragma unroll
            for (int r = 0; r < 4; r++) acc[mi][ni][r] = 0.f;

    const int r0 = tid >> 2, c0 = (tid & 3) * 8;
    const int r1 = (tid + 256) >> 2, c1 = ((tid + 256) & 3) * 8;

    auto load_stage = [&](int st, int chunk) {
        const int k0 = chunk * 32;
        const uint32_t base = sm + st * G_ST;
#pragma unroll
        for (int i = 0; i < 2; i++) {
            const int row = i ? r1 : r0, cs = i ? c1 : c0;
            const int gr = m0 + row;
            const int grc = (gr < M) ? gr : (M - 1);
            const int ab = (gr < M) ? 16 : 0;
            const size_t aoff = (size_t)grc * 512 + k0 + cs;
            const size_t woff = (size_t)(n0 + row) * 512 + k0 + cs;
            const uint32_t so = (row * 40 + cs) * 2;
            cp16(base + so,            J.AH + aoff, ab);
            cp16(base + G_PL + so,     J.AL + aoff, ab);
            cp16(base + 2 * G_PL + so, J.WH + woff, 16);
            cp16(base + 3 * G_PL + so, J.WL + woff, 16);
        }
    };

    load_stage(0, 0);
    CP_COMMIT();

    for (int chunk = 0; chunk < 16; chunk++) {
        const int st = chunk & 1;
        if (chunk + 1 < 16) {
            load_stage(st ^ 1, chunk + 1);
            CP_COMMIT();
            CP_WAIT(1);
        } else {
            CP_WAIT(0);
        }
        __syncthreads();

        bf16 (*AsH)[40] = (bf16(*)[40])(dsm + st * G_ST);
        bf16 (*AsL)[40] = (bf16(*)[40])(dsm + st * G_ST + G_PL);
        bf16 (*BsH)[40] = (bf16(*)[40])(dsm + st * G_ST + 2 * G_PL);
        bf16 (*BsL)[40] = (bf16(*)[40])(dsm + st * G_ST + 3 * G_PL);

        uint32_t ah[2][2][4], al[2][2][4];
#pragma unroll
        for (int mi = 0; mi < 2; mi++) {
            const int r = wm * 32 + mi * 16 + a_r;
#pragma unroll
            for (int ks = 0; ks < 2; ks++) {
                const int c = ks * 16 + a_c;
                ldsm_x4(ah[mi][ks], smem_addr(&AsH[r][c]));
                ldsm_x4(al[mi][ks], smem_addr(&AsL[r][c]));
            }
        }
#pragma unroll
        for (int ni = 0; ni < 8; ni++) {
            const int r = wn * 64 + ni * 8 + b_r;
            uint32_t bh4[4], bl4[4];
            ldsm_x4(bh4, smem_addr(&BsH[r][b_c]));
            ldsm_x4(bl4, smem_addr(&BsL[r][b_c]));
#pragma unroll
            for (int mi = 0; mi < 2; mi++) {
#pragma unroll
                for (int ks = 0; ks < 2; ks++) {
                    mma_bf16(acc[mi][ni], ah[mi][ks], bh4[2 * ks], bh4[2 * ks + 1]);
                    mma_bf16(acc[mi][ni], ah[mi][ks], bl4[2 * ks], bl4[2 * ks + 1]);
                    mma_bf16(acc[mi][ni], al[mi][ks], bh4[2 * ks], bh4[2 * ks + 1]);
                }
            }
        }
        __syncthreads();
    }

    const int tr = lane >> 2, tc = (lane & 3) * 2;
#pragma unroll
    for (int mi = 0; mi < 2; mi++) {
#pragma unroll
        for (int ni = 0; ni < 8; ni++) {
            const int n = n0 + wn * 64 + ni * 8 + tc;
            const float b0 = J.bias[n], b1 = J.bias[n + 1];
            float s0 = 1.f, s1 = 1.f;
            if (J.scale) { s0 = J.scale[n]; s1 = J.scale[n + 1]; }
#pragma unroll
            for (int half = 0; half < 2; half++) {
                const int m = m0 + wm * 32 + mi * 16 + tr + half * 8;
                if (m >= M) continue;
                const float x = (acc[mi][ni][half * 2 + 0] + b0) * s0;
                const float y = (acc[mi][ni][half * 2 + 1] + b1) * s1;
                const size_t off = (size_t)m * 512 + n;
                if (J.Cf) *(float2*)(J.Cf + off) = make_float2(x, y);
                if (J.CH) {
                    uint32_t hi, lo; split2(x, y, hi, lo);
                    *(uint32_t*)(J.CH + off) = hi;
                    *(uint32_t*)(J.CL + off) = lo;
                }
            }
        }
    }
}

// ================= logits: 64q x 128k (two 64k subtiles per CTA), 3 CTAs/SM =================
// phase A: QH@0 QL@5120 K0H@10240 K0L@15360 K1H@20480 K1L@25600 (64x40 each) -> 30720
// phase B: XH@0 XL@9216 Y0H@18432 Y0L@27648 Y1H@36864 Y1L@46080 (64x72 each) -> 55296
// stage:   float[64][68] @55296 (17408) -> total 72704
constexpr uint32_t LOGITS_SMEM = 72704;
constexpr uint32_t L_STG = 55296;
constexpr float RESCUE_BAND = 1e-4f;

__global__ __launch_bounds__(256, 3) void logits_hmma(const float* __restrict__ bias,
                                                      float* __restrict__ FR)
{
    extern __shared__ char dsm[];
    const uint32_t sm = smem_addr(dsm);
    const int tid = threadIdx.x;
    const int wid = tid >> 5, lane = tid & 31;
    const int wm = wid & 1, wn = wid >> 1;           // 2 m-warps x 4 n-warps
    const int bh = blockIdx.z, b = bh >> 3, h = bh & 7;
    const int q0 = blockIdx.y * 64, kbase = blockIdx.x * 128;
    const int a_r = lane & 15, a_c = (lane >> 4) * 8;
    const int b_r = lane & 7,  b_c = (lane >> 3) * 8;
    const int tr = lane >> 2,  tc = (lane & 3) * 2;
    const float bias0 = bias[0];

    // ---- load phase A: Q, K0, K1 (64x32 hi/lo each) ----
    {
        const int row = tid >> 2, cs = (tid & 3) * 8;
        const uint32_t so = row * 80 + cs * 2;
        const int q = q0 + row;
        const int qc = (q < T) ? q : (T - 1);
        const int qb = (q < T) ? 16 : 0;
        const size_t qoff = ((size_t)bh * T + qc) * 32 + cs;
        cp16(sm + so,        g_chH + qoff, qb);
        cp16(sm + 5120 + so, g_chL + qoff, qb);
#pragma unroll
        for (int sub = 0; sub < 2; sub++) {
            const int k = kbase + sub * 64 + row;
            const int kc = (k < T) ? k : (T - 1);
            const int kb = (k < T) ? 16 : 0;
            const size_t koff = ((size_t)bh * T + kc) * 32 + cs;
            cp16(sm + 10240 + sub * 10240 + so, g_ctH + koff, kb);
            cp16(sm + 15360 + sub * 10240 + so, g_ctL + koff, kb);
        }
    }
    CP_COMMIT();
    CP_WAIT(0);
    __syncthreads();

    float acc[2][2][4];
    uint32_t adjm[2], unc[2];

    // ---- phase A: Q frags loaded once, reused across both k subtiles ----
    {
        bf16 (*QH)[40] = (bf16(*)[40])(dsm);
        bf16 (*QL)[40] = (bf16(*)[40])(dsm + 5120);
        uint32_t qh[2][2][4], ql[2][2][4];
#pragma unroll
        for (int mi = 0; mi < 2; mi++) {
            const int r = wm * 32 + mi * 16 + a_r;
#pragma unroll
            for (int ks = 0; ks < 2; ks++) {
                ldsm_x4(qh[mi][ks], smem_addr(&QH[r][ks * 16 + a_c]));
                ldsm_x4(ql[mi][ks], smem_addr(&QL[r][ks * 16 + a_c]));
            }
        }
#pragma unroll
        for (int sub = 0; sub < 2; sub++) {
            bf16 (*KH)[40] = (bf16(*)[40])(dsm + 10240 + sub * 10240);
            bf16 (*KL)[40] = (bf16(*)[40])(dsm + 15360 + sub * 10240);
#pragma unroll
            for (int mi = 0; mi < 2; mi++)
#pragma unroll
                for (int ni = 0; ni < 2; ni++)
#pragma unroll
                    for (int r = 0; r < 4; r++) acc[mi][ni][r] = 0.f;
#pragma unroll
            for (int ni = 0; ni < 2; ni++) {
                const int r = wn * 16 + ni * 8 + b_r;
                uint32_t bh4[4], bl4[4];
                ldsm_x4(bh4, smem_addr(&KH[r][b_c]));
                ldsm_x4(bl4, smem_addr(&KL[r][b_c]));
#pragma unroll
                for (int mi = 0; mi < 2; mi++) {
#pragma unroll
                    for (int ks = 0; ks < 2; ks++) {
                        mma_bf16(acc[mi][ni], qh[mi][ks], bh4[2 * ks], bh4[2 * ks + 1]);
                        mma_bf16(acc[mi][ni], qh[mi][ks], bl4[2 * ks], bl4[2 * ks + 1]);
                        mma_bf16(acc[mi][ni], ql[mi][ks], bh4[2 * ks], bh4[2 * ks + 1]);
                    }
                }
            }
            // masks for this subtile
            const int ksub = kbase + sub * 64;
            uint32_t am = 0u, um = 0u;
#pragma unroll
            for (int mi = 0; mi < 2; mi++)
#pragma unroll
                for (int ni = 0; ni < 2; ni++)
#pragma unroll
                    for (int r = 0; r < 4; r++) {
                        const int q = q0 + wm * 32 + mi * 16 + tr + (r >> 1) * 8;
                        const int k = ksub + wn * 16 + ni * 8 + tc + (r & 1);
                        const bool valid = (q < T) && (k < T) && (k != 0) && (k != q);
                        if (valid) {
                            const float ts = acc[mi][ni][r] + bias0;
                            const int idx = (mi * 2 + ni) * 4 + r;
                            if (fabsf(ts) < RESCUE_BAND) um |= 1u << idx;
                            if (ts > 0.f)                am |= 1u << idx;
                        }
                    }
            adjm[sub] = am;
            unc[sub] = um;
        }
    }
    __syncthreads();   // all phase A smem reads done

    // ---- issue phase B loads: X, Y0, Y1 (64x64 hi/lo each) ----
#pragma unroll
    for (int i = 0; i < 2; i++) {
        const int s = tid + 256 * i;
        const int row = s >> 3, cs = (s & 7) * 8;
        const uint32_t so = row * 144 + cs * 2;
        const int q = q0 + row;
        const int qc = (q < T) ? q : (T - 1);
        const int qb = (q < T) ? 16 : 0;
        const size_t xoff = ((size_t)(b * T + qc)) * 512 + h * 64 + cs;
        cp16(sm + so,        g_fhH + xoff, qb);
        cp16(sm + 9216 + so, g_fhL + xoff, qb);
#pragma unroll
        for (int sub = 0; sub < 2; sub++) {
            const int k = kbase + sub * 64 + row;
            const int kc = (k < T) ? k : (T - 1);
            const int kb = (k < T) ? 16 : 0;
            const size_t yoff = ((size_t)(b * T + kc)) * 512 + h * 64 + cs;
            cp16(sm + 18432 + sub * 18432 + so, g_ftH + yoff, kb);
            cp16(sm + 27648 + sub * 18432 + so, g_ftL + yoff, kb);
        }
    }
    CP_COMMIT();
    CP_WAIT(0);
    __syncthreads();

    // ---- phase B + epilogue, per subtile ----
    bf16 (*XH)[72] = (bf16(*)[72])(dsm);
    bf16 (*XL)[72] = (bf16(*)[72])(dsm + 9216);
    float (*stg)[68] = (float(*)[68])(dsm + L_STG);

#pragma unroll
    for (int sub = 0; sub < 2; sub++) {
        bf16 (*YH)[72] = (bf16(*)[72])(dsm + 18432 + sub * 18432);
        bf16 (*YL)[72] = (bf16(*)[72])(dsm + 27648 + sub * 18432);
#pragma unroll
        for (int mi = 0; mi < 2; mi++)
#pragma unroll
            for (int ni = 0; ni < 2; ni++)
#pragma unroll
                for (int r = 0; r < 4; r++) acc[mi][ni][r] = 0.f;
#pragma unroll
        for (int kk = 0; kk < 64; kk += 32) {
            uint32_t ah[2][2][4], al[2][2][4];
#pragma unroll
            for (int mi = 0; mi < 2; mi++) {
                const int r = wm * 32 + mi * 16 + a_r;
#pragma unroll
                for (int ks = 0; ks < 2; ks++) {
                    const int c = kk + ks * 16 + a_c;
                    ldsm_x4(ah[mi][ks], smem_addr(&XH[r][c]));
                    ldsm_x4(al[mi][ks], smem_addr(&XL[r][c]));
                }
            }
#pragma unroll
            for (int ni = 0; ni < 2; ni++) {
                const int r = wn * 16 + ni * 8 + b_r;
                uint32_t bh4[4], bl4[4];
                ldsm_x4(bh4, smem_addr(&YH[r][kk + b_c]));
                ldsm_x4(bl4, smem_addr(&YL[r][kk + b_c]));
#pragma unroll
                for (int mi = 0; mi < 2; mi++) {
#pragma unroll
                    for (int ks = 0; ks < 2; ks++) {
                        mma_bf16(acc[mi][ni], ah[mi][ks], bh4[2 * ks], bh4[2 * ks + 1]);
                        mma_bf16(acc[mi][ni], ah[mi][ks], bl4[2 * ks], bl4[2 * ks + 1]);
                        mma_bf16(acc[mi][ni], al[mi][ks], bh4[2 * ks], bh4[2 * ks + 1]);
                    }
                }
            }
        }

        // stage masked logits (stg region is disjoint from X/Y smem)
        const int ksub = kbase + sub * 64;
        __syncthreads();   // prior subtile's FR-store reads of stg complete
#pragma unroll
        for (int mi = 0; mi < 2; mi++) {
#pragma unroll
            for (int ni = 0; ni < 2; ni++) {
#pragma unroll
                for (int r = 0; r < 4; r++) {
                    const int ql = wm * 32 + mi * 16 + tr + (r >> 1) * 8;
                    const int kl = wn * 16 + ni * 8 + tc + (r & 1);
                    const int idx = (mi * 2 + ni) * 4 + r;
                    bool abit;
                    if ((unc[sub] >> idx) & 1u) {
                        const float* cq = g_chf + ((size_t)bh * T + q0 + ql) * 24;
                        const float* ck = g_ctf + ((size_t)bh * T + ksub + kl) * 24;
                        float d = 0.f;
#pragma unroll
                        for (int c = 0; c < 22; c++) d = fmaf(cq[c], ck[c], d);
                        abit = (d + bias0 > 0.f);
                    } else {
                        abit = (adjm[sub] >> idx) & 1u;
                    }
                    float v = acc[mi][ni][r] * 0.125f;
                    if (!abit) v -= 10000.0f;
                    stg[ql][kl] = v;
                }
            }
        }
        __syncthreads();

        // coalesced FR store for this subtile
        if (ksub < T) {
            const int kmax = T - ksub;
#pragma unroll
            for (int r = 0; r < 8; r++) {
                const int row = wid * 8 + r;
                const int q = q0 + row;
                if (q >= T) break;
                float* fr = FR + ((size_t)bh * T + q) * T + ksub;
#pragma unroll
                for (int j = 0; j < 2; j++) {
                    const int col = lane + 32 * j;
                    if (col < kmax) fr[col] = stg[row][col];
                }
            }
        }
    }
}

// ================= softmax: single-pass (validated) =================
__global__ __launch_bounds__(256) void softmax_kernel(float* __restrict__ FR)
{
    __shared__ float sred[8];
    const int tid = threadIdx.x;
    const int wid = tid >> 5, lane = tid & 31;
    float* base = FR + (size_t)blockIdx.x * T;
    bf16* ph = g_pH + (size_t)blockIdx.x * TP;
    bf16* pl = g_pL + (size_t)blockIdx.x * TP;

    float e[4];
    int n = 0;
    float s = 0.f;
    for (int i = tid; i < T; i += 256) { e[n] = __expf(base[i]); s += e[n]; n++; }
#pragma unroll
    for (int o = 16; o; o >>= 1) s += __shfl_xor_sync(0xffffffffu, s, o);
    if (lane == 0) sred[wid] = s;
    __syncthreads();
    s = 0.f;
#pragma unroll
    for (int w = 0; w < 8; w++) s += sred[w];
    const float inv = 1.0f / s;
    n = 0;
    for (int i = tid; i < T; i += 256) {
        const float p = e[n] * inv;
        base[i] = p;
        const bf16 hi = __float2bfloat16_rn(p);
        ph[i] = hi;
        pl[i] = __float2bfloat16_rn(p - __bfloat162float(hi));
        n++;
    }
}

// ================= pipelined AV (known good; no cap) =================
constexpr uint32_t AV_PP = 128 * 40 * 2;
constexpr uint32_t AV_VP = 32 * 72 * 2;
constexpr uint32_t AV_ST = 2 * AV_PP + 2 * AV_VP;
constexpr uint32_t AV_SMEM = 2 * AV_ST;

__global__ __launch_bounds__(256) void av_hmma()
{
    extern __shared__ char dsm[];
    const uint32_t sm = smem_addr(dsm);
    const int tid = threadIdx.x;
    const int wid = tid >> 5, lane = tid & 31;
    const int wm = wid & 3, wn = wid >> 2;
    const int bh = blockIdx.y, b = bh >> 3, h = bh & 7;
    const int q0 = blockIdx.x * 128;
    const int a_r = lane & 15, a_c = (lane >> 4) * 8;
    const int tr = lane >> 2, tc = (lane & 3) * 2;

    float acc[2][4][4];
#pragma unroll
    for (int mi = 0; mi < 2; mi++)
#pragma unroll
        for (int ni = 0; ni < 4; ni++)
#pragma unroll
            for (int r = 0; r < 4; r++) acc[mi][ni][r] = 0.f;

    const int pr0 = tid >> 2, pc0 = (tid & 3) * 8;
    const int pr1 = (tid + 256) >> 2, pc1 = ((tid + 256) & 3) * 8;
    const int vr = tid >> 3, vc = (tid & 7) * 8;

    auto load_stage = [&](int st, int k0) {
        const uint32_t base = sm + st * AV_ST;
#pragma unroll
        for (int i = 0; i < 2; i++) {
            const int row = i ? pr1 : pr0, c8 = i ? pc1 : pc0;
            const int q = q0 + row;
            const int qc = (q < T) ? q : (T - 1);
            const int pb = (q < T) ? 16 : 0;
            const size_t off = ((size_t)bh * T + qc) * TP + k0 + c8;
            const uint32_t so = (row * 40 + c8) * 2;
            cp16(base + so,         g_pH + off, pb);
            cp16(base + AV_PP + so, g_pL + off, pb);
        }
        {
            const int kv = k0 + vr;
            const int kc = (kv < T) ? kv : (T - 1);
            const int vb = (kv < T) ? 16 : 0;
            const size_t off = ((size_t)(b * T + kc)) * 512 + h * 64 + vc;
            const uint32_t so = (vr * 72 + vc) * 2;
            cp16(base + 2 * AV_PP + so,         g_fvH + off, vb);
            cp16(base + 2 * AV_PP + AV_VP + so, g_fvL + off, vb);
        }
    };

    load_stage(0, 0);
    CP_COMMIT();

    constexpr int NCHUNK = TP / 32;
    for (int chunk = 0; chunk < NCHUNK; chunk++) {
        const int st = chunk & 1;
        if (chunk + 1 < NCHUNK) {
            load_stage(st ^ 1, (chunk + 1) * 32);
            CP_COMMIT();
            CP_WAIT(1);
        } else {
            CP_WAIT(0);
        }
        __syncthreads();

        bf16 (*PsH)[40] = (bf16(*)[40])(dsm + st * AV_ST);
        bf16 (*PsL)[40] = (bf16(*)[40])(dsm + st * AV_ST + AV_PP);
        bf16 (*VsH)[72] = (bf16(*)[72])(dsm + st * AV_ST + 2 * AV_PP);
        bf16 (*VsL)[72] = (bf16(*)[72])(dsm + st * AV_ST + 2 * AV_PP + AV_VP);

        uint32_t ah[2][2][4], al[2][2][4];
#pragma unroll
        for (int mi = 0; mi < 2; mi++) {
            const int r = wm * 32 + mi * 16 + a_r;
#pragma unroll
            for (int ks = 0; ks < 2; ks++) {
                const int c = ks * 16 + a_c;
                ldsm_x4(ah[mi][ks], smem_addr(&PsH[r][c]));
                ldsm_x4(al[mi][ks], smem_addr(&PsL[r][c]));
            }
        }
#pragma unroll
        for (int ni = 0; ni < 4; ni++) {
            const int nb = wn * 32 + ni * 8;
            uint32_t bh4[4], bl4[4];
            ldsm_x4_t(bh4, smem_addr(&VsH[lane][nb]));
            ldsm_x4_t(bl4, smem_addr(&VsL[lane][nb]));
#pragma unroll
            for (int mi = 0; mi < 2; mi++) {
#pragma unroll
                for (int ks = 0; ks < 2; ks++) {
                    mma_bf16(acc[mi][ni], ah[mi][ks], bh4[2 * ks], bh4[2 * ks + 1]);
                    mma_bf16(acc[mi][ni], ah[mi][ks], bl4[2 * ks], bl4[2 * ks + 1]);
                    mma_bf16(acc[mi][ni], al[mi][ks], bh4[2 * ks], bh4[2 * ks + 1]);
                }
            }
        }
        __syncthreads();
    }

#pragma unroll
    for (int mi = 0; mi < 2; mi++) {
#pragma unroll
        for (int ni = 0; ni < 4; ni++) {
            const int n = wn * 32 + ni * 8 + tc;
#pragma unroll
            for (int half = 0; half < 2; half++) {
                const int q = q0 + wm * 32 + mi * 16 + tr + half * 8;
                if (q >= T) continue;
                const float x = acc[mi][ni][half * 2 + 0];
                const float y = acc[mi][ni][half * 2 + 1];
                uint32_t hi, lo; split2(x, y, hi, lo);
                const size_t off = ((size_t)(b * T + q)) * 512 + h * 64 + n;
                *(uint32_t*)(g_xaH + off) = hi;
                *(uint32_t*)(g_xaL + off) = lo;
            }
        }
    }
}

// ---------------- launcher ----------------
extern "C" void kernel_launch(void* const* d_in, const int* in_sizes, int n_in,
                              void* d_out, int out_size)
{
    const float* x_head = (const float*)d_in[0];
    const float* x_tail = (const float*)d_in[1];
    const int*   ids    = (const int*)  d_in[2];
    const float* Wh     = (const float*)d_in[3];
    const float* bh     = (const float*)d_in[4];
    const float* Wv     = (const float*)d_in[5];
    const float* bv     = (const float*)d_in[6];
    const float* Wo     = (const float*)d_in[7];
    const float* bo     = (const float*)d_in[8];
    const float* rel    = (const float*)d_in[9];
    const float* colh   = (const float*)d_in[10];
    const float* colt   = (const float*)d_in[11];
    const float* bias   = (const float*)d_in[12];

    float* out = (float*)d_out;
    float* FR  = out + X_ELEMS;

    bf16 *xhH, *xhL, *xtH, *xtL, *WhH, *WhL, *WvH, *WvL, *WoH, *WoL;
    bf16 *fhH, *fhL, *ftH, *ftL, *fvH, *fvL, *xaH, *xaL;
    cudaGetSymbolAddress((void**)&xhH, g_xhH); cudaGetSymbolAddress((void**)&xhL, g_xhL);
    cudaGetSymbolAddress((void**)&xtH, g_xtH); cudaGetSymbolAddress((void**)&xtL, g_xtL);
    cudaGetSymbolAddress((void**)&WhH, g_WhH); cudaGetSymbolAddress((void**)&WhL, g_WhL);
    cudaGetSymbolAddress((void**)&WvH, g_WvH); cudaGetSymbolAddress((void**)&WvL, g_WvL);
    cudaGetSymbolAddress((void**)&WoH, g_WoH); cudaGetSymbolAddress((void**)&WoL, g_WoL);
    cudaGetSymbolAddress((void**)&fhH, g_fhH); cudaGetSymbolAddress((void**)&fhL, g_fhL);
    cudaGetSymbolAddress((void**)&ftH, g_ftH); cudaGetSymbolAddress((void**)&ftL, g_ftL);
    cudaGetSymbolAddress((void**)&fvH, g_fvH); cudaGetSymbolAddress((void**)&fvL, g_fvL);
    cudaGetSymbolAddress((void**)&xaH, g_xaH); cudaGetSymbolAddress((void**)&xaL, g_xaL);

    cudaFuncSetAttribute(gemm_batched, cudaFuncAttributeMaxDynamicSharedMemorySize, GEMM_SMEM);
    cudaFuncSetAttribute(logits_hmma, cudaFuncAttributeMaxDynamicSharedMemorySize, LOGITS_SMEM);
    cudaFuncSetAttribute(av_hmma, cudaFuncAttributeMaxDynamicSharedMemorySize, AV_SMEM);

    // launch 1: prep (1D right-sized grid)
    prep_kernel<<<PREP_BLOCKS, 256>>>(x_head, x_tail, Wh, Wv, Wo, colh, colt, ids);
    // launch 2: projections
    Jobs3 pj;
    pj.j[0] = { xhH, xhL, WhH, WhL, bh, rel,     nullptr, fhH, fhL };
    pj.j[1] = { xtH, xtL, WhH, WhL, bh, nullptr, nullptr, ftH, ftL };
    pj.j[2] = { xtH, xtL, WvH, WvL, bv, nullptr, nullptr, fvH, fvL };
    gemm_batched<<<dim3(4, (BT + 127) / 128, 3), 256, GEMM_SMEM>>>(pj, BT);
    // launch 3: logits (64q x 128k tiles, two subtiles per CTA)
    dim3 gLog((T + 127) / 128, (T + 63) / 64, B * H);   // (7, 13, 64)
    logits_hmma<<<gLog, 256, LOGITS_SMEM>>>(bias, FR);
    // launch 4: softmax
    softmax_kernel<<<B * H * T, 256>>>(FR);
    // launch 5: AV
    dim3 gAV((T + 127) / 128, B * H);
    av_hmma<<<gAV, 256, AV_SMEM>>>();
    // launch 6: output projection
    Jobs3 oj;
    oj.j[0] = { xaH, xaL, WoH, WoL, bo, nullptr, out, nullptr, nullptr };
    oj.j[1] = oj.j[0];
    oj.j[2] = oj.j[0];
    gemm_batched<<<dim3(4, (BT + 127) / 128, 1), 256, GEMM_SMEM>>>(oj, BT);
}